// round 4
// baseline (speedup 1.0000x reference)
#include <cuda_runtime.h>
#include <cstdint>

namespace {

constexpr int Bv = 2, Hv = 16, Sv = 2048, Dv = 64;
constexpr int BM = 64;    // query rows per CTA
constexpr int BN = 32;    // kv rows per tile
constexpr int KS2 = 68;   // uint2 stride for sK rows (68 % 16 == 4 -> conflict-free LDS.64)
constexpr int VS = 72;    // float stride for sV rows (72 % 32 == 8 -> conflict-free)
constexpr int PS = 36;    // float stride for mask/P buffer (36 % 32 == 4 -> 4g+t, perfect)
constexpr float QSCALE = 0.125f * 1.44269504089f;  // 1/sqrt(64) * log2(e)

__device__ __forceinline__ uint32_t f2tf(float f) {
    uint32_t r;
    asm("cvt.rna.tf32.f32 %0, %1;" : "=r"(r) : "f"(f));
    return r;
}

__device__ __forceinline__ void mma8(float* c, const uint32_t* a, const uint32_t* b) {
    asm volatile(
        "mma.sync.aligned.m16n8k8.row.col.f32.tf32.tf32.f32 "
        "{%0,%1,%2,%3}, {%4,%5,%6,%7}, {%8,%9}, {%0,%1,%2,%3};"
        : "+f"(c[0]), "+f"(c[1]), "+f"(c[2]), "+f"(c[3])
        : "r"(a[0]), "r"(a[1]), "r"(a[2]), "r"(a[3]), "r"(b[0]), "r"(b[1]));
}

__global__ void __launch_bounds__(128, 3)
attn_kernel(const float* __restrict__ q, const float* __restrict__ k,
            const float* __restrict__ v, const int* __restrict__ mask,
            float* __restrict__ out) {
    __shared__ uint2    sK[BN * KS2];   // K tile pre-split to tf32 (hi, lo)
    __shared__ uint32_t sV[BN * VS];    // V tile pre-converted to tf32, layout [k][n]
    __shared__ float    sPM[BM * PS];   // mask bias, then reused for tf32 P staging

    const int tid = threadIdx.x;
    const int warp = tid >> 5;
    const int lane = tid & 31;
    const int g = lane >> 2;
    const int t = lane & 3;
    const int r0 = warp * 16 + g;
    const int r1 = r0 + 8;

    const int bh = blockIdx.y;
    const int b  = bh >> 4;          // H = 16
    const int q0 = blockIdx.x * BM;

    const float* qg = q + ((size_t)bh * Sv + q0) * Dv;
    const float* kg = k + (size_t)bh * Sv * Dv;
    const float* vg = v + (size_t)bh * Sv * Dv;
    const int*   mg = mask + ((size_t)b * Sv + q0) * Sv;
    float*       og = out + ((size_t)bh * Sv + q0) * Dv;

    // ---- Q A-fragments: scaled, split to tf32 hi/lo ONCE, held in registers ----
    uint32_t qh[8][4], ql[8][4];
#pragma unroll
    for (int kc = 0; kc < 8; kc++) {
        const int kk = kc * 8;
        float f0 = qg[(size_t)r0 * Dv + kk + t] * QSCALE;
        float f1 = qg[(size_t)r1 * Dv + kk + t] * QSCALE;
        float f2 = qg[(size_t)r0 * Dv + kk + t + 4] * QSCALE;
        float f3 = qg[(size_t)r1 * Dv + kk + t + 4] * QSCALE;
        qh[kc][0] = f2tf(f0); qh[kc][1] = f2tf(f1);
        qh[kc][2] = f2tf(f2); qh[kc][3] = f2tf(f3);
        ql[kc][0] = f2tf(f0 - __uint_as_float(qh[kc][0]));
        ql[kc][1] = f2tf(f1 - __uint_as_float(qh[kc][1]));
        ql[kc][2] = f2tf(f2 - __uint_as_float(qh[kc][2]));
        ql[kc][3] = f2tf(f3 - __uint_as_float(qh[kc][3]));
    }

    float o[8][4];
#pragma unroll
    for (int i = 0; i < 8; i++)
#pragma unroll
        for (int j = 0; j < 4; j++) o[i][j] = 0.f;
    float m0 = -1e30f, m1 = -1e30f, l0 = 0.f, l1 = 0.f;

    for (int kt = 0; kt < Sv / BN; kt++) {
        __syncthreads();  // previous tile fully consumed before overwrite
        const int kbase = kt * BN;

        // ---- K tile: load f32, split to tf32 hi/lo, store uint2 ----
        for (int i = tid; i < BN * 16; i += 128) {
            int row = i >> 4, c4 = i & 15;
            float4 kv4 = *reinterpret_cast<const float4*>(kg + (size_t)(kbase + row) * Dv + c4 * 4);
            uint2* dk = &sK[row * KS2 + c4 * 4];
            float fv[4] = {kv4.x, kv4.y, kv4.z, kv4.w};
#pragma unroll
            for (int j = 0; j < 4; j++) {
                uint32_t hi = f2tf(fv[j]);
                uint32_t lo = f2tf(fv[j] - __uint_as_float(hi));
                dk[j] = make_uint2(hi, lo);
            }
        }
        // ---- V tile: pre-convert to tf32 ----
        for (int i = tid; i < BN * 16; i += 128) {
            int row = i >> 4, c4 = i & 15;
            float4 vv4 = *reinterpret_cast<const float4*>(vg + (size_t)(kbase + row) * Dv + c4 * 4);
            uint32_t* dv = &sV[row * VS + c4 * 4];
            dv[0] = f2tf(vv4.x); dv[1] = f2tf(vv4.y);
            dv[2] = f2tf(vv4.z); dv[3] = f2tf(vv4.w);
        }
        // ---- mask tile: pre-convert to additive bias ----
        for (int i = tid; i < BM * 8; i += 128) {
            int row = i >> 3, c4 = i & 7;
            int4 mi = *reinterpret_cast<const int4*>(mg + (size_t)row * Sv + kbase + c4 * 4);
            float* d = &sPM[row * PS + c4 * 4];
            d[0] = mi.x ? 0.f : -1e9f;
            d[1] = mi.y ? 0.f : -1e9f;
            d[2] = mi.z ? 0.f : -1e9f;
            d[3] = mi.w ? 0.f : -1e9f;
        }
        __syncthreads();

        // ---- S = Q @ K^T (3xtf32: qh*bh + ql*bh + qh*bl) ----
        float sacc[4][4];
#pragma unroll
        for (int nc = 0; nc < 4; nc++)
#pragma unroll
            for (int j = 0; j < 4; j++) sacc[nc][j] = 0.f;

#pragma unroll
        for (int kc = 0; kc < 8; kc++) {
            const int kk = kc * 8;
#pragma unroll
            for (int nc = 0; nc < 4; nc++) {
                uint2 b0 = sK[(nc * 8 + g) * KS2 + kk + t];
                uint2 b1 = sK[(nc * 8 + g) * KS2 + kk + t + 4];
                uint32_t bhv[2] = {b0.x, b1.x};
                uint32_t blv[2] = {b0.y, b1.y};
                mma8(sacc[nc], qh[kc], bhv);
                mma8(sacc[nc], ql[kc], bhv);
                mma8(sacc[nc], qh[kc], blv);
            }
        }

        // ---- mask bias + online softmax (log2 domain) ----
        float mx0 = -1e30f, mx1 = -1e30f;
#pragma unroll
        for (int nc = 0; nc < 4; nc++) {
            int c0 = nc * 8 + 2 * t;
            sacc[nc][0] += sPM[r0 * PS + c0];
            sacc[nc][1] += sPM[r0 * PS + c0 + 1];
            sacc[nc][2] += sPM[r1 * PS + c0];
            sacc[nc][3] += sPM[r1 * PS + c0 + 1];
            mx0 = fmaxf(mx0, fmaxf(sacc[nc][0], sacc[nc][1]));
            mx1 = fmaxf(mx1, fmaxf(sacc[nc][2], sacc[nc][3]));
        }
        mx0 = fmaxf(mx0, __shfl_xor_sync(0xffffffffu, mx0, 1));
        mx0 = fmaxf(mx0, __shfl_xor_sync(0xffffffffu, mx0, 2));
        mx1 = fmaxf(mx1, __shfl_xor_sync(0xffffffffu, mx1, 1));
        mx1 = fmaxf(mx1, __shfl_xor_sync(0xffffffffu, mx1, 2));

        float m0n = fmaxf(m0, mx0), m1n = fmaxf(m1, mx1);
        float a0 = exp2f(m0 - m0n), a1 = exp2f(m1 - m1n);
        m0 = m0n; m1 = m1n;

        float rs0 = 0.f, rs1 = 0.f;
#pragma unroll
        for (int nc = 0; nc < 4; nc++) {
            int c0 = nc * 8 + 2 * t;
            float p00 = exp2f(sacc[nc][0] - m0n);
            float p01 = exp2f(sacc[nc][1] - m0n);
            float p10 = exp2f(sacc[nc][2] - m1n);
            float p11 = exp2f(sacc[nc][3] - m1n);
            rs0 += p00 + p01; rs1 += p10 + p11;
            // store pre-converted to tf32 bits
            sPM[r0 * PS + c0]     = __uint_as_float(f2tf(p00));
            sPM[r0 * PS + c0 + 1] = __uint_as_float(f2tf(p01));
            sPM[r1 * PS + c0]     = __uint_as_float(f2tf(p10));
            sPM[r1 * PS + c0 + 1] = __uint_as_float(f2tf(p11));
        }
        rs0 += __shfl_xor_sync(0xffffffffu, rs0, 1);
        rs0 += __shfl_xor_sync(0xffffffffu, rs0, 2);
        rs1 += __shfl_xor_sync(0xffffffffu, rs1, 1);
        rs1 += __shfl_xor_sync(0xffffffffu, rs1, 2);
        l0 = l0 * a0 + rs0;
        l1 = l1 * a1 + rs1;

        // rescale O only when the running max actually moved (warp-uniform branch)
        if (__any_sync(0xffffffffu, (a0 < 1.f) | (a1 < 1.f))) {
#pragma unroll
            for (int nc = 0; nc < 8; nc++) {
                o[nc][0] *= a0; o[nc][1] *= a0;
                o[nc][2] *= a1; o[nc][3] *= a1;
            }
        }
        __syncwarp();  // publish this warp's P rows before fragment reads

        // ---- O += P @ V (tf32) ----
#pragma unroll
        for (int kc = 0; kc < 4; kc++) {
            const int kk = kc * 8;
            uint32_t pa[4] = {__float_as_uint(sPM[r0 * PS + kk + t]),
                              __float_as_uint(sPM[r1 * PS + kk + t]),
                              __float_as_uint(sPM[r0 * PS + kk + t + 4]),
                              __float_as_uint(sPM[r1 * PS + kk + t + 4])};
#pragma unroll
            for (int nc = 0; nc < 8; nc++) {
                uint32_t pb[2] = {sV[(kk + t) * VS + nc * 8 + g],
                                  sV[(kk + t + 4) * VS + nc * 8 + g]};
                mma8(o[nc], pa, pb);
            }
        }
    }

    // ---- epilogue ----
    float inv0 = 1.f / l0, inv1 = 1.f / l1;
#pragma unroll
    for (int nc = 0; nc < 8; nc++) {
        int c0 = nc * 8 + 2 * t;
        float2 w0 = make_float2(o[nc][0] * inv0, o[nc][1] * inv0);
        float2 w1 = make_float2(o[nc][2] * inv1, o[nc][3] * inv1);
        *reinterpret_cast<float2*>(og + (size_t)r0 * Dv + c0) = w0;
        *reinterpret_cast<float2*>(og + (size_t)r1 * Dv + c0) = w1;
    }
}

}  // namespace

extern "C" void kernel_launch(void* const* d_in, const int* in_sizes, int n_in,
                              void* d_out, int out_size) {
    const float* q = (const float*)d_in[0];
    const float* k = (const float*)d_in[1];
    const float* v = (const float*)d_in[2];
    const int* mask = (const int*)d_in[3];
    float* out = (float*)d_out;

    dim3 grid(Sv / BM, Bv * Hv);  // (32, 32)
    dim3 block(128);
    attn_kernel<<<grid, block>>>(q, k, v, mask, out);
}

// round 6
// speedup vs baseline: 2.9934x; 2.9934x over previous
#include <cuda_runtime.h>
#include <cstdint>

namespace {

constexpr int Bv = 2, Hv = 16, Sv = 2048, Dv = 64;
constexpr int BM = 64;   // query rows per CTA
constexpr int BN = 32;   // kv rows per tile
constexpr int KS = 68;   // sK uint32 stride: 68%32==4 -> b-frag banks 4g+t, conflict-free
constexpr int VS = 72;   // sV uint32 stride: 72%32==8 -> banks 8t+g, conflict-free
constexpr int PS = 36;   // sPM float stride (P staging)
constexpr float QSCALE = 0.125f * 1.44269504089f;  // 1/sqrt(64) * log2(e)

__device__ __forceinline__ uint32_t f2tf(float f) {
    uint32_t r;
    asm("cvt.rna.tf32.f32 %0, %1;" : "=r"(r) : "f"(f));
    return r;
}

__device__ __forceinline__ void mma8(float* c, const uint32_t* a, const uint32_t* b) {
    asm volatile(
        "mma.sync.aligned.m16n8k8.row.col.f32.tf32.tf32.f32 "
        "{%0,%1,%2,%3}, {%4,%5,%6,%7}, {%8,%9}, {%0,%1,%2,%3};"
        : "+f"(c[0]), "+f"(c[1]), "+f"(c[2]), "+f"(c[3])
        : "r"(a[0]), "r"(a[1]), "r"(a[2]), "r"(a[3]), "r"(b[0]), "r"(b[1]));
}

__global__ void __launch_bounds__(128, 4)
attn_kernel(const float* __restrict__ q, const float* __restrict__ k,
            const float* __restrict__ v, const int* __restrict__ mask,
            float* __restrict__ out) {
    __shared__ uint32_t sK[BN * KS];   // K tile as tf32
    __shared__ uint32_t sV[BN * VS];   // V tile as tf32
    __shared__ float    sPM[BM * PS];  // tf32 P staging (warp-private row bands)

    const int tid = threadIdx.x;
    const int warp = tid >> 5;
    const int lane = tid & 31;
    const int g = lane >> 2;
    const int t = lane & 3;
    const int r0 = warp * 16 + g;
    const int r1 = r0 + 8;

    const int bh = blockIdx.y;
    const int b  = bh >> 4;          // H = 16
    const int q0 = blockIdx.x * BM;

    const float* qg = q + ((size_t)bh * Sv + q0) * Dv;
    const float* kg = k + (size_t)bh * Sv * Dv;
    const float* vg = v + (size_t)bh * Sv * Dv;
    const int*   mg = mask + ((size_t)b * Sv + q0) * Sv;
    float*       og = out + ((size_t)bh * Sv + q0) * Dv;

    // ---- Q A-fragments: scaled, converted to tf32 ONCE, held in registers (32 regs) ----
    uint32_t qh[8][4];
#pragma unroll
    for (int kc = 0; kc < 8; kc++) {
        const int kk = kc * 8;
        qh[kc][0] = f2tf(qg[(size_t)r0 * Dv + kk + t]     * QSCALE);
        qh[kc][1] = f2tf(qg[(size_t)r1 * Dv + kk + t]     * QSCALE);
        qh[kc][2] = f2tf(qg[(size_t)r0 * Dv + kk + t + 4] * QSCALE);
        qh[kc][3] = f2tf(qg[(size_t)r1 * Dv + kk + t + 4] * QSCALE);
    }

    float o[8][4];
#pragma unroll
    for (int i = 0; i < 8; i++)
#pragma unroll
        for (int j = 0; j < 4; j++) o[i][j] = 0.f;
    float m0 = -1e30f, m1 = -1e30f, l0 = 0.f, l1 = 0.f;

    for (int kt = 0; kt < Sv / BN; kt++) {
        __syncthreads();  // previous tile fully consumed before overwrite
        const int kbase = kt * BN;

        // ---- mask prefetch: direct gmem -> regs, issued early to overlap MMAs ----
        int2 mk0[4], mk1[4];
#pragma unroll
        for (int nc = 0; nc < 4; nc++) {
            mk0[nc] = *reinterpret_cast<const int2*>(mg + (size_t)r0 * Sv + kbase + nc * 8 + 2 * t);
            mk1[nc] = *reinterpret_cast<const int2*>(mg + (size_t)r1 * Sv + kbase + nc * 8 + 2 * t);
        }

        // ---- K tile: f32 -> tf32, STS.128 ----
#pragma unroll
        for (int i = 0; i < 4; i++) {
            int idx = tid + i * 128;
            int row = idx >> 4, c4 = idx & 15;
            float4 kv4 = *reinterpret_cast<const float4*>(kg + (size_t)(kbase + row) * Dv + c4 * 4);
            uint4 w = make_uint4(f2tf(kv4.x), f2tf(kv4.y), f2tf(kv4.z), f2tf(kv4.w));
            *reinterpret_cast<uint4*>(&sK[row * KS + c4 * 4]) = w;
        }
        // ---- V tile: f32 -> tf32, STS.128 ----
#pragma unroll
        for (int i = 0; i < 4; i++) {
            int idx = tid + i * 128;
            int row = idx >> 4, c4 = idx & 15;
            float4 vv4 = *reinterpret_cast<const float4*>(vg + (size_t)(kbase + row) * Dv + c4 * 4);
            uint4 w = make_uint4(f2tf(vv4.x), f2tf(vv4.y), f2tf(vv4.z), f2tf(vv4.w));
            *reinterpret_cast<uint4*>(&sV[row * VS + c4 * 4]) = w;
        }
        __syncthreads();

        // ---- S = Q @ K^T (1x tf32) ----
        float sacc[4][4];
#pragma unroll
        for (int nc = 0; nc < 4; nc++)
#pragma unroll
            for (int j = 0; j < 4; j++) sacc[nc][j] = 0.f;

#pragma unroll
        for (int kc = 0; kc < 8; kc++) {
            const int kk = kc * 8;
#pragma unroll
            for (int nc = 0; nc < 4; nc++) {
                uint32_t bv[2] = {sK[(nc * 8 + g) * KS + kk + t],
                                  sK[(nc * 8 + g) * KS + kk + t + 4]};
                mma8(sacc[nc], qh[kc], bv);
            }
        }

        // ---- mask select + online softmax (log2 domain) ----
        float mx0 = -1e30f, mx1 = -1e30f;
#pragma unroll
        for (int nc = 0; nc < 4; nc++) {
            sacc[nc][0] = mk0[nc].x ? sacc[nc][0] : -1e9f;
            sacc[nc][1] = mk0[nc].y ? sacc[nc][1] : -1e9f;
            sacc[nc][2] = mk1[nc].x ? sacc[nc][2] : -1e9f;
            sacc[nc][3] = mk1[nc].y ? sacc[nc][3] : -1e9f;
            mx0 = fmaxf(mx0, fmaxf(sacc[nc][0], sacc[nc][1]));
            mx1 = fmaxf(mx1, fmaxf(sacc[nc][2], sacc[nc][3]));
        }
        mx0 = fmaxf(mx0, __shfl_xor_sync(0xffffffffu, mx0, 1));
        mx0 = fmaxf(mx0, __shfl_xor_sync(0xffffffffu, mx0, 2));
        mx1 = fmaxf(mx1, __shfl_xor_sync(0xffffffffu, mx1, 1));
        mx1 = fmaxf(mx1, __shfl_xor_sync(0xffffffffu, mx1, 2));

        float m0n = fmaxf(m0, mx0), m1n = fmaxf(m1, mx1);
        float a0 = exp2f(m0 - m0n), a1 = exp2f(m1 - m1n);
        m0 = m0n; m1 = m1n;

        float rs0 = 0.f, rs1 = 0.f;
#pragma unroll
        for (int nc = 0; nc < 4; nc++) {
            int c0 = nc * 8 + 2 * t;
            float p00 = exp2f(sacc[nc][0] - m0n);
            float p01 = exp2f(sacc[nc][1] - m0n);
            float p10 = exp2f(sacc[nc][2] - m1n);
            float p11 = exp2f(sacc[nc][3] - m1n);
            rs0 += p00 + p01; rs1 += p10 + p11;
            sPM[r0 * PS + c0]     = __uint_as_float(f2tf(p00));
            sPM[r0 * PS + c0 + 1] = __uint_as_float(f2tf(p01));
            sPM[r1 * PS + c0]     = __uint_as_float(f2tf(p10));
            sPM[r1 * PS + c0 + 1] = __uint_as_float(f2tf(p11));
        }
        rs0 += __shfl_xor_sync(0xffffffffu, rs0, 1);
        rs0 += __shfl_xor_sync(0xffffffffu, rs0, 2);
        rs1 += __shfl_xor_sync(0xffffffffu, rs1, 1);
        rs1 += __shfl_xor_sync(0xffffffffu, rs1, 2);
        l0 = l0 * a0 + rs0;
        l1 = l1 * a1 + rs1;

        // rescale O only when the running max actually moved (warp-uniform branch)
        if (__any_sync(0xffffffffu, (a0 < 1.f) | (a1 < 1.f))) {
#pragma unroll
            for (int nc = 0; nc < 8; nc++) {
                o[nc][0] *= a0; o[nc][1] *= a0;
                o[nc][2] *= a1; o[nc][3] *= a1;
            }
        }
        __syncwarp();  // publish this warp's P rows (warp-private band of sPM)

        // ---- O += P @ V (tf32) ----
#pragma unroll
        for (int kc = 0; kc < 4; kc++) {
            const int kk = kc * 8;
            uint32_t pa[4] = {__float_as_uint(sPM[r0 * PS + kk + t]),
                              __float_as_uint(sPM[r1 * PS + kk + t]),
                              __float_as_uint(sPM[r0 * PS + kk + t + 4]),
                              __float_as_uint(sPM[r1 * PS + kk + t + 4])};
#pragma unroll
            for (int nc = 0; nc < 8; nc++) {
                uint32_t pb[2] = {sV[(kk + t) * VS + nc * 8 + g],
                                  sV[(kk + t + 4) * VS + nc * 8 + g]};
                mma8(o[nc], pa, pb);
            }
        }
    }

    // ---- epilogue ----
    float inv0 = 1.f / l0, inv1 = 1.f / l1;
#pragma unroll
    for (int nc = 0; nc < 8; nc++) {
        int c0 = nc * 8 + 2 * t;
        float2 w0 = make_float2(o[nc][0] * inv0, o[nc][1] * inv0);
        float2 w1 = make_float2(o[nc][2] * inv1, o[nc][3] * inv1);
        *reinterpret_cast<float2*>(og + (size_t)r0 * Dv + c0) = w0;
        *reinterpret_cast<float2*>(og + (size_t)r1 * Dv + c0) = w1;
    }
}

}  // namespace

extern "C" void kernel_launch(void* const* d_in, const int* in_sizes, int n_in,
                              void* d_out, int out_size) {
    const float* q = (const float*)d_in[0];
    const float* k = (const float*)d_in[1];
    const float* v = (const float*)d_in[2];
    const int* mask = (const int*)d_in[3];
    float* out = (float*)d_out;

    dim3 grid(Sv / BM, Bv * Hv);  // (32, 32)
    dim3 block(128);
    attn_kernel<<<grid, block>>>(q, k, v, mask, out);
}

// round 7
// speedup vs baseline: 3.6461x; 1.2181x over previous
#include <cuda_runtime.h>
#include <cuda_fp16.h>
#include <cstdint>

namespace {

constexpr int Bv = 2, Hv = 16, Sv = 2048, Dv = 64;
constexpr int BM = 64;    // query rows per CTA
constexpr int BN = 32;    // kv rows per tile
constexpr int KS2 = 36;   // sK2 half2 stride (32 data + 4 pad): frag banks (4g+t), conflict-free
constexpr int VS2 = 72;   // sV2 half2 stride (64 data + 8 pad): frag banks (8t+g), conflict-free
constexpr int PS2 = 20;   // sP2 half2 stride (16 data + 4 pad): frag banks (20g+t)%32, conflict-free
constexpr float QSCALE = 0.125f * 1.44269504089f;  // 1/sqrt(64) * log2(e)

__device__ __forceinline__ uint32_t h2(float lo, float hi) {
    __half2 h = __floats2half2_rn(lo, hi);
    return *reinterpret_cast<uint32_t*>(&h);
}

__device__ __forceinline__ void mma16(float* c, const uint32_t* a, const uint32_t* b) {
    asm volatile(
        "mma.sync.aligned.m16n8k16.row.col.f32.f16.f16.f32 "
        "{%0,%1,%2,%3}, {%4,%5,%6,%7}, {%8,%9}, {%0,%1,%2,%3};"
        : "+f"(c[0]), "+f"(c[1]), "+f"(c[2]), "+f"(c[3])
        : "r"(a[0]), "r"(a[1]), "r"(a[2]), "r"(a[3]), "r"(b[0]), "r"(b[1]));
}

__global__ void __launch_bounds__(128, 4)
attn_kernel(const float* __restrict__ q, const float* __restrict__ k,
            const float* __restrict__ v, const int* __restrict__ mask,
            float* __restrict__ out) {
    __shared__ uint32_t sK2[BN * KS2];        // K tile, half2 pairs along d
    __shared__ uint32_t sV2[(BN / 2) * VS2];  // V tile, half2 pairs along k (seq)
    __shared__ uint32_t sP2[BM * PS2];        // P staging, half2 pairs along n

    const int tid = threadIdx.x;
    const int warp = tid >> 5;
    const int lane = tid & 31;
    const int g = lane >> 2;
    const int t = lane & 3;
    const int r0 = warp * 16 + g;
    const int r1 = r0 + 8;

    const int bh = blockIdx.y;
    const int b  = bh >> 4;          // H = 16
    const int q0 = blockIdx.x * BM;

    const float* qg = q + ((size_t)bh * Sv + q0) * Dv;
    const float* kg = k + (size_t)bh * Sv * Dv;
    const float* vg = v + (size_t)bh * Sv * Dv;
    const int*   mg = mask + ((size_t)b * Sv + q0) * Sv;
    float*       og = out + ((size_t)bh * Sv + q0) * Dv;

    // ---- Q A-fragments (fp16 m16n8k16): scaled + converted ONCE, 16 regs ----
    uint32_t qh[4][4];
#pragma unroll
    for (int kc = 0; kc < 4; kc++) {
        const int kk = kc * 16 + 2 * t;
        float2 x0 = *reinterpret_cast<const float2*>(qg + (size_t)r0 * Dv + kk);
        float2 x1 = *reinterpret_cast<const float2*>(qg + (size_t)r1 * Dv + kk);
        float2 x2 = *reinterpret_cast<const float2*>(qg + (size_t)r0 * Dv + kk + 8);
        float2 x3 = *reinterpret_cast<const float2*>(qg + (size_t)r1 * Dv + kk + 8);
        qh[kc][0] = h2(x0.x * QSCALE, x0.y * QSCALE);
        qh[kc][1] = h2(x1.x * QSCALE, x1.y * QSCALE);
        qh[kc][2] = h2(x2.x * QSCALE, x2.y * QSCALE);
        qh[kc][3] = h2(x3.x * QSCALE, x3.y * QSCALE);
    }

    float o[8][4];
#pragma unroll
    for (int i = 0; i < 8; i++)
#pragma unroll
        for (int j = 0; j < 4; j++) o[i][j] = 0.f;
    float m0 = -1e30f, m1 = -1e30f, l0 = 0.f, l1 = 0.f;

    for (int kt = 0; kt < Sv / BN; kt++) {
        __syncthreads();  // previous tile fully consumed before overwrite
        const int kbase = kt * BN;

        // ---- mask prefetch: direct gmem -> regs (overlaps staging + MMAs) ----
        int2 mk0[4], mk1[4];
#pragma unroll
        for (int nc = 0; nc < 4; nc++) {
            mk0[nc] = *reinterpret_cast<const int2*>(mg + (size_t)r0 * Sv + kbase + nc * 8 + 2 * t);
            mk1[nc] = *reinterpret_cast<const int2*>(mg + (size_t)r1 * Sv + kbase + nc * 8 + 2 * t);
        }

        // ---- K tile: 32x64 f32 -> half2 pairs along d; 16 f32/thread, 2x STS.128 ----
        {
            int row = tid >> 2, dseg = tid & 3;
            const float* src = kg + (size_t)(kbase + row) * Dv + dseg * 16;
            float4 a = *reinterpret_cast<const float4*>(src);
            float4 bb = *reinterpret_cast<const float4*>(src + 4);
            float4 c = *reinterpret_cast<const float4*>(src + 8);
            float4 d = *reinterpret_cast<const float4*>(src + 12);
            uint32_t* dst = &sK2[row * KS2 + dseg * 8];
            *reinterpret_cast<uint4*>(dst) =
                make_uint4(h2(a.x, a.y), h2(a.z, a.w), h2(bb.x, bb.y), h2(bb.z, bb.w));
            *reinterpret_cast<uint4*>(dst + 4) =
                make_uint4(h2(c.x, c.y), h2(c.z, c.w), h2(d.x, d.y), h2(d.z, d.w));
        }
        // ---- V tile: 32x64 f32 -> half2 pairs along k; 16 f32/thread, 2x STS.128 ----
        {
            int k2 = tid >> 3, seg = tid & 7;
            const float* s0 = vg + (size_t)(kbase + 2 * k2) * Dv + seg * 8;
            const float* s1 = s0 + Dv;
            float4 a0 = *reinterpret_cast<const float4*>(s0);
            float4 a1 = *reinterpret_cast<const float4*>(s0 + 4);
            float4 b0 = *reinterpret_cast<const float4*>(s1);
            float4 b1 = *reinterpret_cast<const float4*>(s1 + 4);
            uint32_t* dst = &sV2[k2 * VS2 + seg * 8];
            *reinterpret_cast<uint4*>(dst) =
                make_uint4(h2(a0.x, b0.x), h2(a0.y, b0.y), h2(a0.z, b0.z), h2(a0.w, b0.w));
            *reinterpret_cast<uint4*>(dst + 4) =
                make_uint4(h2(a1.x, b1.x), h2(a1.y, b1.y), h2(a1.z, b1.z), h2(a1.w, b1.w));
        }
        __syncthreads();

        // ---- S = Q @ K^T (fp16 m16n8k16, f32 accum) ----
        float sacc[4][4];
#pragma unroll
        for (int nc = 0; nc < 4; nc++)
#pragma unroll
            for (int j = 0; j < 4; j++) sacc[nc][j] = 0.f;

#pragma unroll
        for (int kc = 0; kc < 4; kc++) {
#pragma unroll
            for (int nc = 0; nc < 4; nc++) {
                uint32_t bv[2] = {sK2[(nc * 8 + g) * KS2 + kc * 8 + t],
                                  sK2[(nc * 8 + g) * KS2 + kc * 8 + t + 4]};
                mma16(sacc[nc], qh[kc], bv);
            }
        }

        // ---- mask select + online softmax (log2 domain) ----
        float mx0 = -1e30f, mx1 = -1e30f;
#pragma unroll
        for (int nc = 0; nc < 4; nc++) {
            sacc[nc][0] = mk0[nc].x ? sacc[nc][0] : -1e9f;
            sacc[nc][1] = mk0[nc].y ? sacc[nc][1] : -1e9f;
            sacc[nc][2] = mk1[nc].x ? sacc[nc][2] : -1e9f;
            sacc[nc][3] = mk1[nc].y ? sacc[nc][3] : -1e9f;
            mx0 = fmaxf(mx0, fmaxf(sacc[nc][0], sacc[nc][1]));
            mx1 = fmaxf(mx1, fmaxf(sacc[nc][2], sacc[nc][3]));
        }
        mx0 = fmaxf(mx0, __shfl_xor_sync(0xffffffffu, mx0, 1));
        mx0 = fmaxf(mx0, __shfl_xor_sync(0xffffffffu, mx0, 2));
        mx1 = fmaxf(mx1, __shfl_xor_sync(0xffffffffu, mx1, 1));
        mx1 = fmaxf(mx1, __shfl_xor_sync(0xffffffffu, mx1, 2));

        float m0n = fmaxf(m0, mx0), m1n = fmaxf(m1, mx1);
        float a0 = exp2f(m0 - m0n), a1 = exp2f(m1 - m1n);
        m0 = m0n; m1 = m1n;

        float rs0 = 0.f, rs1 = 0.f;
#pragma unroll
        for (int nc = 0; nc < 4; nc++) {
            float p00 = exp2f(sacc[nc][0] - m0n);
            float p01 = exp2f(sacc[nc][1] - m0n);
            float p10 = exp2f(sacc[nc][2] - m1n);
            float p11 = exp2f(sacc[nc][3] - m1n);
            rs0 += p00 + p01; rs1 += p10 + p11;
            sP2[r0 * PS2 + nc * 4 + t] = h2(p00, p01);
            sP2[r1 * PS2 + nc * 4 + t] = h2(p10, p11);
        }
        rs0 += __shfl_xor_sync(0xffffffffu, rs0, 1);
        rs0 += __shfl_xor_sync(0xffffffffu, rs0, 2);
        rs1 += __shfl_xor_sync(0xffffffffu, rs1, 1);
        rs1 += __shfl_xor_sync(0xffffffffu, rs1, 2);
        l0 = l0 * a0 + rs0;
        l1 = l1 * a1 + rs1;

        // rescale O only when the running max actually moved (warp-uniform branch)
        if (__any_sync(0xffffffffu, (a0 < 1.f) | (a1 < 1.f))) {
#pragma unroll
            for (int nc = 0; nc < 8; nc++) {
                o[nc][0] *= a0; o[nc][1] *= a0;
                o[nc][2] *= a1; o[nc][3] *= a1;
            }
        }
        __syncwarp();  // publish this warp's P rows (warp-private band of sP2)

        // ---- O += P @ V (fp16 m16n8k16) ----
#pragma unroll
        for (int kc2 = 0; kc2 < 2; kc2++) {
            uint32_t pa[4] = {sP2[r0 * PS2 + kc2 * 8 + t],
                              sP2[r1 * PS2 + kc2 * 8 + t],
                              sP2[r0 * PS2 + kc2 * 8 + t + 4],
                              sP2[r1 * PS2 + kc2 * 8 + t + 4]};
#pragma unroll
            for (int nc = 0; nc < 8; nc++) {
                uint32_t pb[2] = {sV2[(kc2 * 8 + t) * VS2 + nc * 8 + g],
                                  sV2[(kc2 * 8 + t + 4) * VS2 + nc * 8 + g]};
                mma16(o[nc], pa, pb);
            }
        }
    }

    // ---- epilogue ----
    float inv0 = 1.f / l0, inv1 = 1.f / l1;
#pragma unroll
    for (int nc = 0; nc < 8; nc++) {
        int c0 = nc * 8 + 2 * t;
        float2 w0 = make_float2(o[nc][0] * inv0, o[nc][1] * inv0);
        float2 w1 = make_float2(o[nc][2] * inv1, o[nc][3] * inv1);
        *reinterpret_cast<float2*>(og + (size_t)r0 * Dv + c0) = w0;
        *reinterpret_cast<float2*>(og + (size_t)r1 * Dv + c0) = w1;
    }
}

}  // namespace

extern "C" void kernel_launch(void* const* d_in, const int* in_sizes, int n_in,
                              void* d_out, int out_size) {
    const float* q = (const float*)d_in[0];
    const float* k = (const float*)d_in[1];
    const float* v = (const float*)d_in[2];
    const int* mask = (const int*)d_in[3];
    float* out = (float*)d_out;

    dim3 grid(Sv / BM, Bv * Hv);  // (32, 32)
    dim3 block(128);
    attn_kernel<<<grid, block>>>(q, k, v, mask, out);
}

// round 10
// speedup vs baseline: 3.7857x; 1.0383x over previous
#include <cuda_runtime.h>
#include <cuda_fp16.h>
#include <cstdint>

namespace {

constexpr int Bv = 2, Hv = 16, Sv = 2048, Dv = 64;
constexpr int BM = 128;   // query rows per CTA (32 per warp)
constexpr int BN = 32;    // kv rows per tile
constexpr int KS2 = 36;   // sK2 half2 stride: frag banks (4g+t), conflict-free
constexpr int VS2 = 72;   // sV2 half2 stride: frag banks (8t+g), conflict-free
constexpr float QSCALE = 0.125f * 1.44269504089f;  // 1/sqrt(64) * log2(e)

__device__ __forceinline__ uint32_t h2(float lo, float hi) {
    __half2 h = __floats2half2_rn(lo, hi);
    return *reinterpret_cast<uint32_t*>(&h);
}

__device__ __forceinline__ void mma16(float* c, const uint32_t* a, const uint32_t* b) {
    asm volatile(
        "mma.sync.aligned.m16n8k16.row.col.f32.f16.f16.f32 "
        "{%0,%1,%2,%3}, {%4,%5,%6,%7}, {%8,%9}, {%0,%1,%2,%3};"
        : "+f"(c[0]), "+f"(c[1]), "+f"(c[2]), "+f"(c[3])
        : "r"(a[0]), "r"(a[1]), "r"(a[2]), "r"(a[3]), "r"(b[0]), "r"(b[1]));
}

__global__ void __launch_bounds__(128, 3)
attn_kernel(const float* __restrict__ q, const float* __restrict__ k,
            const float* __restrict__ v, const int* __restrict__ mask,
            float* __restrict__ out) {
    __shared__ uint32_t sK2[BN * KS2];        // K tile, half2 pairs along d
    __shared__ uint32_t sV2[(BN / 2) * VS2];  // V tile, half2 pairs along kv

    const int tid = threadIdx.x;
    const int warp = tid >> 5;
    const int lane = tid & 31;
    const int g = lane >> 2;
    const int t = lane & 3;
    const int base = warp * 32;
    const int rA0 = base + g;        // frag0 rows rA0, rA0+8
    const int rA1 = base + 16 + g;   // frag1 rows rA1, rA1+8

    const int bh = blockIdx.y;
    const int b  = bh >> 4;          // H = 16
    const int q0 = blockIdx.x * BM;

    const float* qg = q + ((size_t)bh * Sv + q0) * Dv;
    const float* kg = k + (size_t)bh * Sv * Dv;
    const float* vg = v + (size_t)bh * Sv * Dv;
    const int*   mg = mask + ((size_t)b * Sv + q0) * Sv;
    float*       og = out + ((size_t)bh * Sv + q0) * Dv;

    // ---- Q A-fragments for both row-frags: scaled + converted ONCE (32 regs) ----
    uint32_t qh[2][4][4];
#pragma unroll
    for (int f = 0; f < 2; f++) {
        const int rA = base + f * 16 + g, rB = rA + 8;
#pragma unroll
        for (int kc = 0; kc < 4; kc++) {
            const int kk = kc * 16 + 2 * t;
            float2 x0 = *reinterpret_cast<const float2*>(qg + (size_t)rA * Dv + kk);
            float2 x1 = *reinterpret_cast<const float2*>(qg + (size_t)rB * Dv + kk);
            float2 x2 = *reinterpret_cast<const float2*>(qg + (size_t)rA * Dv + kk + 8);
            float2 x3 = *reinterpret_cast<const float2*>(qg + (size_t)rB * Dv + kk + 8);
            qh[f][kc][0] = h2(x0.x * QSCALE, x0.y * QSCALE);
            qh[f][kc][1] = h2(x1.x * QSCALE, x1.y * QSCALE);
            qh[f][kc][2] = h2(x2.x * QSCALE, x2.y * QSCALE);
            qh[f][kc][3] = h2(x3.x * QSCALE, x3.y * QSCALE);
        }
    }

    // Hoisted, incrementing source pointers (kills per-iter IMADs)
    const int kro = tid >> 2, kds = tid & 3;       // K stage mapping
    const int vk2 = tid >> 3, vsg = tid & 7;       // V stage mapping
    const float* kp  = kg + (size_t)kro * Dv + kds * 16;
    const float* vp0 = vg + (size_t)(2 * vk2) * Dv + vsg * 8;
    const float* vp1 = vp0 + Dv;
    const int* mpA0 = mg + (size_t)rA0 * Sv + 2 * t;
    const int* mpB0 = mpA0 + 8 * Sv;
    const int* mpA1 = mg + (size_t)rA1 * Sv + 2 * t;
    const int* mpB1 = mpA1 + 8 * Sv;

    float o0[8][4], o1[8][4];
#pragma unroll
    for (int i = 0; i < 8; i++)
#pragma unroll
        for (int j = 0; j < 4; j++) { o0[i][j] = 0.f; o1[i][j] = 0.f; }
    float m0 = -1e30f, m1 = -1e30f, m2 = -1e30f, m3 = -1e30f;
    float l0 = 0.f, l1 = 0.f, l2 = 0.f, l3 = 0.f;

    for (int kt = 0; kt < Sv / BN; kt++) {
        __syncthreads();  // previous tile fully consumed

        // ---- mask frag0 prefetch (lives through QK MMAs) ----
        int2 mkA0[4], mkB0[4];
#pragma unroll
        for (int nc = 0; nc < 4; nc++) {
            mkA0[nc] = *reinterpret_cast<const int2*>(mpA0 + nc * 8);
            mkB0[nc] = *reinterpret_cast<const int2*>(mpB0 + nc * 8);
        }

        // ---- K tile: 32x64 f32 -> half2 pairs along d ----
        {
            float4 a = *reinterpret_cast<const float4*>(kp);
            float4 bb = *reinterpret_cast<const float4*>(kp + 4);
            float4 c = *reinterpret_cast<const float4*>(kp + 8);
            float4 d = *reinterpret_cast<const float4*>(kp + 12);
            uint32_t* dst = &sK2[kro * KS2 + kds * 8];
            *reinterpret_cast<uint4*>(dst) =
                make_uint4(h2(a.x, a.y), h2(a.z, a.w), h2(bb.x, bb.y), h2(bb.z, bb.w));
            *reinterpret_cast<uint4*>(dst + 4) =
                make_uint4(h2(c.x, c.y), h2(c.z, c.w), h2(d.x, d.y), h2(d.z, d.w));
            kp += BN * Dv;
        }
        // ---- V tile: 32x64 f32 -> half2 pairs along kv ----
        {
            float4 a0 = *reinterpret_cast<const float4*>(vp0);
            float4 a1 = *reinterpret_cast<const float4*>(vp0 + 4);
            float4 b0 = *reinterpret_cast<const float4*>(vp1);
            float4 b1 = *reinterpret_cast<const float4*>(vp1 + 4);
            uint32_t* dst = &sV2[vk2 * VS2 + vsg * 8];
            *reinterpret_cast<uint4*>(dst) =
                make_uint4(h2(a0.x, b0.x), h2(a0.y, b0.y), h2(a0.z, b0.z), h2(a0.w, b0.w));
            *reinterpret_cast<uint4*>(dst + 4) =
                make_uint4(h2(a1.x, b1.x), h2(a1.y, b1.y), h2(a1.z, b1.z), h2(a1.w, b1.w));
            vp0 += BN * Dv; vp1 += BN * Dv;
        }
        __syncthreads();

        // ---- S = Q @ K^T: each b-frag load feeds BOTH row-frags ----
        float s0[4][4], s1[4][4];
#pragma unroll
        for (int nc = 0; nc < 4; nc++)
#pragma unroll
            for (int j = 0; j < 4; j++) { s0[nc][j] = 0.f; s1[nc][j] = 0.f; }

#pragma unroll
        for (int kc = 0; kc < 4; kc++) {
#pragma unroll
            for (int nc = 0; nc < 4; nc++) {
                uint32_t bv[2] = {sK2[(nc * 8 + g) * KS2 + kc * 8 + t],
                                  sK2[(nc * 8 + g) * KS2 + kc * 8 + t + 4]};
                mma16(s0[nc], qh[0][kc], bv);
                mma16(s1[nc], qh[1][kc], bv);
            }
        }

        // ---- softmax frag0 -> register-resident P (pa0) ----
        uint32_t pa0[4][2];
        {
            float mx0 = -1e30f, mx1 = -1e30f;
#pragma unroll
            for (int nc = 0; nc < 4; nc++) {
                s0[nc][0] = mkA0[nc].x ? s0[nc][0] : -1e9f;
                s0[nc][1] = mkA0[nc].y ? s0[nc][1] : -1e9f;
                s0[nc][2] = mkB0[nc].x ? s0[nc][2] : -1e9f;
                s0[nc][3] = mkB0[nc].y ? s0[nc][3] : -1e9f;
                mx0 = fmaxf(mx0, fmaxf(s0[nc][0], s0[nc][1]));
                mx1 = fmaxf(mx1, fmaxf(s0[nc][2], s0[nc][3]));
            }
            mx0 = fmaxf(mx0, __shfl_xor_sync(0xffffffffu, mx0, 1));
            mx0 = fmaxf(mx0, __shfl_xor_sync(0xffffffffu, mx0, 2));
            mx1 = fmaxf(mx1, __shfl_xor_sync(0xffffffffu, mx1, 1));
            mx1 = fmaxf(mx1, __shfl_xor_sync(0xffffffffu, mx1, 2));
            float mn0 = fmaxf(m0, mx0), mn1 = fmaxf(m1, mx1);
            float a0 = exp2f(m0 - mn0), a1 = exp2f(m1 - mn1);
            m0 = mn0; m1 = mn1;
            float rs0 = 0.f, rs1 = 0.f;
#pragma unroll
            for (int nc = 0; nc < 4; nc++) {
                float p00 = exp2f(s0[nc][0] - mn0);
                float p01 = exp2f(s0[nc][1] - mn0);
                float p10 = exp2f(s0[nc][2] - mn1);
                float p11 = exp2f(s0[nc][3] - mn1);
                rs0 += p00 + p01; rs1 += p10 + p11;
                pa0[nc][0] = h2(p00, p01);   // rows g   -> A-frag a0/a2 slots
                pa0[nc][1] = h2(p10, p11);   // rows g+8 -> A-frag a1/a3 slots
            }
            rs0 += __shfl_xor_sync(0xffffffffu, rs0, 1);
            rs0 += __shfl_xor_sync(0xffffffffu, rs0, 2);
            rs1 += __shfl_xor_sync(0xffffffffu, rs1, 1);
            rs1 += __shfl_xor_sync(0xffffffffu, rs1, 2);
            l0 = l0 * a0 + rs0;
            l1 = l1 * a1 + rs1;
            if (__any_sync(0xffffffffu, (a0 < 1.f) | (a1 < 1.f))) {
#pragma unroll
                for (int nc = 0; nc < 8; nc++) {
                    o0[nc][0] *= a0; o0[nc][1] *= a0;
                    o0[nc][2] *= a1; o0[nc][3] *= a1;
                }
            }
        }

        // ---- softmax frag1 -> pa1 ----
        uint32_t pa1[4][2];
        {
            int2 mkA1[4], mkB1[4];
#pragma unroll
            for (int nc = 0; nc < 4; nc++) {
                mkA1[nc] = *reinterpret_cast<const int2*>(mpA1 + nc * 8);
                mkB1[nc] = *reinterpret_cast<const int2*>(mpB1 + nc * 8);
            }
            float mx0 = -1e30f, mx1 = -1e30f;
#pragma unroll
            for (int nc = 0; nc < 4; nc++) {
                s1[nc][0] = mkA1[nc].x ? s1[nc][0] : -1e9f;
                s1[nc][1] = mkA1[nc].y ? s1[nc][1] : -1e9f;
                s1[nc][2] = mkB1[nc].x ? s1[nc][2] : -1e9f;
                s1[nc][3] = mkB1[nc].y ? s1[nc][3] : -1e9f;
                mx0 = fmaxf(mx0, fmaxf(s1[nc][0], s1[nc][1]));
                mx1 = fmaxf(mx1, fmaxf(s1[nc][2], s1[nc][3]));
            }
            mx0 = fmaxf(mx0, __shfl_xor_sync(0xffffffffu, mx0, 1));
            mx0 = fmaxf(mx0, __shfl_xor_sync(0xffffffffu, mx0, 2));
            mx1 = fmaxf(mx1, __shfl_xor_sync(0xffffffffu, mx1, 1));
            mx1 = fmaxf(mx1, __shfl_xor_sync(0xffffffffu, mx1, 2));
            float mn0 = fmaxf(m2, mx0), mn1 = fmaxf(m3, mx1);
            float a0 = exp2f(m2 - mn0), a1 = exp2f(m3 - mn1);
            m2 = mn0; m3 = mn1;
            float rs0 = 0.f, rs1 = 0.f;
#pragma unroll
            for (int nc = 0; nc < 4; nc++) {
                float p00 = exp2f(s1[nc][0] - mn0);
                float p01 = exp2f(s1[nc][1] - mn0);
                float p10 = exp2f(s1[nc][2] - mn1);
                float p11 = exp2f(s1[nc][3] - mn1);
                rs0 += p00 + p01; rs1 += p10 + p11;
                pa1[nc][0] = h2(p00, p01);
                pa1[nc][1] = h2(p10, p11);
            }
            rs0 += __shfl_xor_sync(0xffffffffu, rs0, 1);
            rs0 += __shfl_xor_sync(0xffffffffu, rs0, 2);
            rs1 += __shfl_xor_sync(0xffffffffu, rs1, 1);
            rs1 += __shfl_xor_sync(0xffffffffu, rs1, 2);
            l2 = l2 * a0 + rs0;
            l3 = l3 * a1 + rs1;
            if (__any_sync(0xffffffffu, (a0 < 1.f) | (a1 < 1.f))) {
#pragma unroll
                for (int nc = 0; nc < 8; nc++) {
                    o1[nc][0] *= a0; o1[nc][1] *= a0;
                    o1[nc][2] *= a1; o1[nc][3] *= a1;
                }
            }
        }

        // ---- O += P @ V: each pb load feeds BOTH row-frags ----
#pragma unroll
        for (int kc2 = 0; kc2 < 2; kc2++) {
            uint32_t a0v[4] = {pa0[2 * kc2][0], pa0[2 * kc2][1],
                               pa0[2 * kc2 + 1][0], pa0[2 * kc2 + 1][1]};
            uint32_t a1v[4] = {pa1[2 * kc2][0], pa1[2 * kc2][1],
                               pa1[2 * kc2 + 1][0], pa1[2 * kc2 + 1][1]};
#pragma unroll
            for (int nc = 0; nc < 8; nc++) {
                uint32_t pb[2] = {sV2[(kc2 * 8 + t) * VS2 + nc * 8 + g],
                                  sV2[(kc2 * 8 + t + 4) * VS2 + nc * 8 + g]};
                mma16(o0[nc], a0v, pb);
                mma16(o1[nc], a1v, pb);
            }
        }

        mpA0 += BN; mpB0 += BN; mpA1 += BN; mpB1 += BN;
    }

    // ---- epilogue ----
    {
        float i0 = 1.f / l0, i1 = 1.f / l1, i2 = 1.f / l2, i3 = 1.f / l3;
#pragma unroll
        for (int nc = 0; nc < 8; nc++) {
            int c0 = nc * 8 + 2 * t;
            *reinterpret_cast<float2*>(og + (size_t)rA0 * Dv + c0) =
                make_float2(o0[nc][0] * i0, o0[nc][1] * i0);
            *reinterpret_cast<float2*>(og + (size_t)(rA0 + 8) * Dv + c0) =
                make_float2(o0[nc][2] * i1, o0[nc][3] * i1);
            *reinterpret_cast<float2*>(og + (size_t)rA1 * Dv + c0) =
                make_float2(o1[nc][0] * i2, o1[nc][1] * i2);
            *reinterpret_cast<float2*>(og + (size_t)(rA1 + 8) * Dv + c0) =
                make_float2(o1[nc][2] * i3, o1[nc][3] * i3);
        }
    }
}

}  // namespace

extern "C" void kernel_launch(void* const* d_in, const int* in_sizes, int n_in,
                              void* d_out, int out_size) {
    const float* q = (const float*)d_in[0];
    const float* k = (const float*)d_in[1];
    const float* v = (const float*)d_in[2];
    const int* mask = (const int*)d_in[3];
    float* out = (float*)d_out;

    dim3 grid(Sv / BM, Bv * Hv);  // (16, 32)
    dim3 block(128);
    attn_kernel<<<grid, block>>>(q, k, v, mask, out);
}

// round 11
// speedup vs baseline: 4.9133x; 1.2979x over previous
#include <cuda_runtime.h>
#include <cuda_fp16.h>
#include <cstdint>

namespace {

constexpr int Bv = 2, Hv = 16, Sv = 2048, Dv = 64;
constexpr int BM = 128;   // query rows per CTA (32 per warp)
constexpr int BN = 32;    // kv rows per tile
constexpr int NT = Sv / BN;
constexpr int KS2 = 36;   // sK2 half2 stride: frag banks (4g+t), conflict-free
constexpr int VS2 = 72;   // sV2 half2 stride: frag banks (8t+g), conflict-free
constexpr float QSCALE = 0.125f * 1.44269504089f;  // 1/sqrt(64) * log2(e)

__device__ __forceinline__ uint32_t h2(float lo, float hi) {
    __half2 h = __floats2half2_rn(lo, hi);
    return *reinterpret_cast<uint32_t*>(&h);
}

__device__ __forceinline__ void mma16(float* c, const uint32_t* a, const uint32_t* b) {
    asm volatile(
        "mma.sync.aligned.m16n8k16.row.col.f32.f16.f16.f32 "
        "{%0,%1,%2,%3}, {%4,%5,%6,%7}, {%8,%9}, {%0,%1,%2,%3};"
        : "+f"(c[0]), "+f"(c[1]), "+f"(c[2]), "+f"(c[3])
        : "r"(a[0]), "r"(a[1]), "r"(a[2]), "r"(a[3]), "r"(b[0]), "r"(b[1]));
}

__global__ void __launch_bounds__(128, 2)
attn_kernel(const float* __restrict__ q, const float* __restrict__ k,
            const float* __restrict__ v, const int* __restrict__ mask,
            float* __restrict__ out) {
    __shared__ uint32_t sK2[2][BN * KS2];        // double-buffered K tile (half2 along d)
    __shared__ uint32_t sV2[2][(BN / 2) * VS2];  // double-buffered V tile (half2 along kv)

    const int tid = threadIdx.x;
    const int warp = tid >> 5;
    const int lane = tid & 31;
    const int g = lane >> 2;
    const int t = lane & 3;
    const int base = warp * 32;
    const int rA0 = base + g;
    const int rA1 = base + 16 + g;

    const int bh = blockIdx.y;
    const int b  = bh >> 4;          // H = 16
    const int q0 = blockIdx.x * BM;

    const float* qg = q + ((size_t)bh * Sv + q0) * Dv;
    const float* kg = k + (size_t)bh * Sv * Dv;
    const float* vg = v + (size_t)bh * Sv * Dv;
    const int*   mg = mask + ((size_t)b * Sv + q0) * Sv;
    float*       og = out + ((size_t)bh * Sv + q0) * Dv;

    // ---- Q A-fragments for both row-frags: scaled + converted ONCE (32 regs) ----
    uint32_t qh[2][4][4];
#pragma unroll
    for (int f = 0; f < 2; f++) {
        const int rA = base + f * 16 + g, rB = rA + 8;
#pragma unroll
        for (int kc = 0; kc < 4; kc++) {
            const int kk = kc * 16 + 2 * t;
            float2 x0 = *reinterpret_cast<const float2*>(qg + (size_t)rA * Dv + kk);
            float2 x1 = *reinterpret_cast<const float2*>(qg + (size_t)rB * Dv + kk);
            float2 x2 = *reinterpret_cast<const float2*>(qg + (size_t)rA * Dv + kk + 8);
            float2 x3 = *reinterpret_cast<const float2*>(qg + (size_t)rB * Dv + kk + 8);
            qh[f][kc][0] = h2(x0.x * QSCALE, x0.y * QSCALE);
            qh[f][kc][1] = h2(x1.x * QSCALE, x1.y * QSCALE);
            qh[f][kc][2] = h2(x2.x * QSCALE, x2.y * QSCALE);
            qh[f][kc][3] = h2(x3.x * QSCALE, x3.y * QSCALE);
        }
    }

    // Stage mappings + hoisted incrementing pointers
    const int kro = tid >> 2, kds = tid & 3;
    const int vk2 = tid >> 3, vsg = tid & 7;
    const float* kp  = kg + (size_t)kro * Dv + kds * 16;
    const float* vp0 = vg + (size_t)(2 * vk2) * Dv + vsg * 8;
    const float* vp1 = vp0 + Dv;
    const int* mpA0 = mg + (size_t)rA0 * Sv + 2 * t;
    const int* mpB0 = mpA0 + 8 * Sv;
    const int* mpA1 = mg + (size_t)rA1 * Sv + 2 * t;
    const int* mpB1 = mpA1 + 8 * Sv;

    // ---- prefetch tile 0 into registers ----
    float4 fkA = *reinterpret_cast<const float4*>(kp);
    float4 fkB = *reinterpret_cast<const float4*>(kp + 4);
    float4 fkC = *reinterpret_cast<const float4*>(kp + 8);
    float4 fkD = *reinterpret_cast<const float4*>(kp + 12);
    float4 fvA0 = *reinterpret_cast<const float4*>(vp0);
    float4 fvA1 = *reinterpret_cast<const float4*>(vp0 + 4);
    float4 fvB0 = *reinterpret_cast<const float4*>(vp1);
    float4 fvB1 = *reinterpret_cast<const float4*>(vp1 + 4);
    kp += BN * Dv; vp0 += BN * Dv; vp1 += BN * Dv;

    float o0[8][4], o1[8][4];
#pragma unroll
    for (int i = 0; i < 8; i++)
#pragma unroll
        for (int j = 0; j < 4; j++) { o0[i][j] = 0.f; o1[i][j] = 0.f; }
    float m0 = -1e30f, m1 = -1e30f, m2 = -1e30f, m3 = -1e30f;
    float l0 = 0.f, l1 = 0.f, l2 = 0.f, l3 = 0.f;

    for (int kt = 0; kt < NT; kt++) {
        const int cur = kt & 1;

        // ---- store prefetched regs -> smem[cur] (convert f32 -> half2 here) ----
        {
            uint32_t* dK = &sK2[cur][kro * KS2 + kds * 8];
            *reinterpret_cast<uint4*>(dK) =
                make_uint4(h2(fkA.x, fkA.y), h2(fkA.z, fkA.w), h2(fkB.x, fkB.y), h2(fkB.z, fkB.w));
            *reinterpret_cast<uint4*>(dK + 4) =
                make_uint4(h2(fkC.x, fkC.y), h2(fkC.z, fkC.w), h2(fkD.x, fkD.y), h2(fkD.z, fkD.w));
            uint32_t* dV = &sV2[cur][vk2 * VS2 + vsg * 8];
            *reinterpret_cast<uint4*>(dV) =
                make_uint4(h2(fvA0.x, fvB0.x), h2(fvA0.y, fvB0.y), h2(fvA0.z, fvB0.z), h2(fvA0.w, fvB0.w));
            *reinterpret_cast<uint4*>(dV + 4) =
                make_uint4(h2(fvA1.x, fvB1.x), h2(fvA1.y, fvB1.y), h2(fvA1.z, fvB1.z), h2(fvA1.w, fvB1.w));
        }
        __syncthreads();  // single barrier per iteration (double buffer)

        // ---- prefetch NEXT tile into regs: LDGs hidden under the compute below ----
        if (kt + 1 < NT) {
            fkA = *reinterpret_cast<const float4*>(kp);
            fkB = *reinterpret_cast<const float4*>(kp + 4);
            fkC = *reinterpret_cast<const float4*>(kp + 8);
            fkD = *reinterpret_cast<const float4*>(kp + 12);
            fvA0 = *reinterpret_cast<const float4*>(vp0);
            fvA1 = *reinterpret_cast<const float4*>(vp0 + 4);
            fvB0 = *reinterpret_cast<const float4*>(vp1);
            fvB1 = *reinterpret_cast<const float4*>(vp1 + 4);
            kp += BN * Dv; vp0 += BN * Dv; vp1 += BN * Dv;
        }

        // ---- mask frag0 prefetch ----
        int2 mkA0[4], mkB0[4];
#pragma unroll
        for (int nc = 0; nc < 4; nc++) {
            mkA0[nc] = *reinterpret_cast<const int2*>(mpA0 + nc * 8);
            mkB0[nc] = *reinterpret_cast<const int2*>(mpB0 + nc * 8);
        }

        // ---- S = Q @ K^T: each b-frag load feeds BOTH row-frags ----
        float s0[4][4], s1[4][4];
#pragma unroll
        for (int nc = 0; nc < 4; nc++)
#pragma unroll
            for (int j = 0; j < 4; j++) { s0[nc][j] = 0.f; s1[nc][j] = 0.f; }

#pragma unroll
        for (int kc = 0; kc < 4; kc++) {
#pragma unroll
            for (int nc = 0; nc < 4; nc++) {
                uint32_t bv[2] = {sK2[cur][(nc * 8 + g) * KS2 + kc * 8 + t],
                                  sK2[cur][(nc * 8 + g) * KS2 + kc * 8 + t + 4]};
                mma16(s0[nc], qh[0][kc], bv);
                mma16(s1[nc], qh[1][kc], bv);
            }
        }

        // ---- softmax frag0 -> register-resident P ----
        uint32_t pa0[4][2];
        {
            float mx0 = -1e30f, mx1 = -1e30f;
#pragma unroll
            for (int nc = 0; nc < 4; nc++) {
                s0[nc][0] = mkA0[nc].x ? s0[nc][0] : -1e9f;
                s0[nc][1] = mkA0[nc].y ? s0[nc][1] : -1e9f;
                s0[nc][2] = mkB0[nc].x ? s0[nc][2] : -1e9f;
                s0[nc][3] = mkB0[nc].y ? s0[nc][3] : -1e9f;
                mx0 = fmaxf(mx0, fmaxf(s0[nc][0], s0[nc][1]));
                mx1 = fmaxf(mx1, fmaxf(s0[nc][2], s0[nc][3]));
            }
            mx0 = fmaxf(mx0, __shfl_xor_sync(0xffffffffu, mx0, 1));
            mx0 = fmaxf(mx0, __shfl_xor_sync(0xffffffffu, mx0, 2));
            mx1 = fmaxf(mx1, __shfl_xor_sync(0xffffffffu, mx1, 1));
            mx1 = fmaxf(mx1, __shfl_xor_sync(0xffffffffu, mx1, 2));
            float mn0 = fmaxf(m0, mx0), mn1 = fmaxf(m1, mx1);
            float a0 = exp2f(m0 - mn0), a1 = exp2f(m1 - mn1);
            m0 = mn0; m1 = mn1;
            float rs0 = 0.f, rs1 = 0.f;
#pragma unroll
            for (int nc = 0; nc < 4; nc++) {
                float p00 = exp2f(s0[nc][0] - mn0);
                float p01 = exp2f(s0[nc][1] - mn0);
                float p10 = exp2f(s0[nc][2] - mn1);
                float p11 = exp2f(s0[nc][3] - mn1);
                rs0 += p00 + p01; rs1 += p10 + p11;
                pa0[nc][0] = h2(p00, p01);
                pa0[nc][1] = h2(p10, p11);
            }
            rs0 += __shfl_xor_sync(0xffffffffu, rs0, 1);
            rs0 += __shfl_xor_sync(0xffffffffu, rs0, 2);
            rs1 += __shfl_xor_sync(0xffffffffu, rs1, 1);
            rs1 += __shfl_xor_sync(0xffffffffu, rs1, 2);
            l0 = l0 * a0 + rs0;
            l1 = l1 * a1 + rs1;
            if (__any_sync(0xffffffffu, (a0 < 1.f) | (a1 < 1.f))) {
#pragma unroll
                for (int nc = 0; nc < 8; nc++) {
                    o0[nc][0] *= a0; o0[nc][1] *= a0;
                    o0[nc][2] *= a1; o0[nc][3] *= a1;
                }
            }
        }

        // ---- softmax frag1 ----
        uint32_t pa1[4][2];
        {
            int2 mkA1[4], mkB1[4];
#pragma unroll
            for (int nc = 0; nc < 4; nc++) {
                mkA1[nc] = *reinterpret_cast<const int2*>(mpA1 + nc * 8);
                mkB1[nc] = *reinterpret_cast<const int2*>(mpB1 + nc * 8);
            }
            float mx0 = -1e30f, mx1 = -1e30f;
#pragma unroll
            for (int nc = 0; nc < 4; nc++) {
                s1[nc][0] = mkA1[nc].x ? s1[nc][0] : -1e9f;
                s1[nc][1] = mkA1[nc].y ? s1[nc][1] : -1e9f;
                s1[nc][2] = mkB1[nc].x ? s1[nc][2] : -1e9f;
                s1[nc][3] = mkB1[nc].y ? s1[nc][3] : -1e9f;
                mx0 = fmaxf(mx0, fmaxf(s1[nc][0], s1[nc][1]));
                mx1 = fmaxf(mx1, fmaxf(s1[nc][2], s1[nc][3]));
            }
            mx0 = fmaxf(mx0, __shfl_xor_sync(0xffffffffu, mx0, 1));
            mx0 = fmaxf(mx0, __shfl_xor_sync(0xffffffffu, mx0, 2));
            mx1 = fmaxf(mx1, __shfl_xor_sync(0xffffffffu, mx1, 1));
            mx1 = fmaxf(mx1, __shfl_xor_sync(0xffffffffu, mx1, 2));
            float mn0 = fmaxf(m2, mx0), mn1 = fmaxf(m3, mx1);
            float a0 = exp2f(m2 - mn0), a1 = exp2f(m3 - mn1);
            m2 = mn0; m3 = mn1;
            float rs0 = 0.f, rs1 = 0.f;
#pragma unroll
            for (int nc = 0; nc < 4; nc++) {
                float p00 = exp2f(s1[nc][0] - mn0);
                float p01 = exp2f(s1[nc][1] - mn0);
                float p10 = exp2f(s1[nc][2] - mn1);
                float p11 = exp2f(s1[nc][3] - mn1);
                rs0 += p00 + p01; rs1 += p10 + p11;
                pa1[nc][0] = h2(p00, p01);
                pa1[nc][1] = h2(p10, p11);
            }
            rs0 += __shfl_xor_sync(0xffffffffu, rs0, 1);
            rs0 += __shfl_xor_sync(0xffffffffu, rs0, 2);
            rs1 += __shfl_xor_sync(0xffffffffu, rs1, 1);
            rs1 += __shfl_xor_sync(0xffffffffu, rs1, 2);
            l2 = l2 * a0 + rs0;
            l3 = l3 * a1 + rs1;
            if (__any_sync(0xffffffffu, (a0 < 1.f) | (a1 < 1.f))) {
#pragma unroll
                for (int nc = 0; nc < 8; nc++) {
                    o1[nc][0] *= a0; o1[nc][1] *= a0;
                    o1[nc][2] *= a1; o1[nc][3] *= a1;
                }
            }
        }

        // ---- O += P @ V: each pb load feeds BOTH row-frags ----
#pragma unroll
        for (int kc2 = 0; kc2 < 2; kc2++) {
            uint32_t a0v[4] = {pa0[2 * kc2][0], pa0[2 * kc2][1],
                               pa0[2 * kc2 + 1][0], pa0[2 * kc2 + 1][1]};
            uint32_t a1v[4] = {pa1[2 * kc2][0], pa1[2 * kc2][1],
                               pa1[2 * kc2 + 1][0], pa1[2 * kc2 + 1][1]};
#pragma unroll
            for (int nc = 0; nc < 8; nc++) {
                uint32_t pb[2] = {sV2[cur][(kc2 * 8 + t) * VS2 + nc * 8 + g],
                                  sV2[cur][(kc2 * 8 + t + 4) * VS2 + nc * 8 + g]};
                mma16(o0[nc], a0v, pb);
                mma16(o1[nc], a1v, pb);
            }
        }

        mpA0 += BN; mpB0 += BN; mpA1 += BN; mpB1 += BN;
    }

    // ---- epilogue ----
    {
        float i0 = 1.f / l0, i1 = 1.f / l1, i2 = 1.f / l2, i3 = 1.f / l3;
#pragma unroll
        for (int nc = 0; nc < 8; nc++) {
            int c0 = nc * 8 + 2 * t;
            *reinterpret_cast<float2*>(og + (size_t)rA0 * Dv + c0) =
                make_float2(o0[nc][0] * i0, o0[nc][1] * i0);
            *reinterpret_cast<float2*>(og + (size_t)(rA0 + 8) * Dv + c0) =
                make_float2(o0[nc][2] * i1, o0[nc][3] * i1);
            *reinterpret_cast<float2*>(og + (size_t)rA1 * Dv + c0) =
                make_float2(o1[nc][0] * i2, o1[nc][1] * i2);
            *reinterpret_cast<float2*>(og + (size_t)(rA1 + 8) * Dv + c0) =
                make_float2(o1[nc][2] * i3, o1[nc][3] * i3);
        }
    }
}

}  // namespace

extern "C" void kernel_launch(void* const* d_in, const int* in_sizes, int n_in,
                              void* d_out, int out_size) {
    const float* q = (const float*)d_in[0];
    const float* k = (const float*)d_in[1];
    const float* v = (const float*)d_in[2];
    const int* mask = (const int*)d_in[3];
    float* out = (float*)d_out;

    dim3 grid(Sv / BM, Bv * Hv);  // (16, 32)
    dim3 block(128);
    attn_kernel<<<grid, block>>>(q, k, v, mask, out);
}

// round 14
// speedup vs baseline: 5.3129x; 1.0813x over previous
#include <cuda_runtime.h>
#include <cuda_fp16.h>
#include <cstdint>

namespace {

constexpr int Bv = 2, Hv = 16, Sv = 2048, Dv = 64;
constexpr int BM = 128;   // query rows per CTA (32 per warp)
constexpr int BN = 32;    // kv rows per tile
constexpr int NT = Sv / BN;
constexpr int KS2 = 36;   // sK2 half2 stride: frag banks (4g+t), conflict-free
constexpr int VS2 = 72;   // sV2 half2 stride: frag banks (8t+g), conflict-free
constexpr float QSCALE = 0.125f * 1.44269504089f;  // 1/sqrt(64) * log2(e)

// Packed mask bits: pm[b][col_group][row], col_group = 32 cols. 1 MB scratch.
__device__ uint32_t d_pm[(size_t)Bv * (Sv / 32) * Sv];

__global__ void __launch_bounds__(256)
pack_mask_kernel(const int* __restrict__ mask) {
    int idx = blockIdx.x * blockDim.x + threadIdx.x;
    int lane = idx & 31;
    int w = idx >> 5;                    // word index = (b*64 + cg)*2048 + row
    int row = w & (Sv - 1);
    int cg  = (w >> 11) & (Sv / 32 - 1);
    int b   = w >> 17;
    int val = mask[((size_t)b * Sv + row) * Sv + cg * 32 + lane];
    uint32_t bits = __ballot_sync(0xffffffffu, val != 0);
    if (lane == 0) d_pm[w] = bits;
}

__device__ __forceinline__ uint32_t h2(float lo, float hi) {
    __half2 h = __floats2half2_rn(lo, hi);
    return *reinterpret_cast<uint32_t*>(&h);
}

__device__ __forceinline__ void mma16(float* c, const uint32_t* a, const uint32_t* b) {
    asm volatile(
        "mma.sync.aligned.m16n8k16.row.col.f32.f16.f16.f32 "
        "{%0,%1,%2,%3}, {%4,%5,%6,%7}, {%8,%9}, {%0,%1,%2,%3};"
        : "+f"(c[0]), "+f"(c[1]), "+f"(c[2]), "+f"(c[3])
        : "r"(a[0]), "r"(a[1]), "r"(a[2]), "r"(a[3]), "r"(b[0]), "r"(b[1]));
}

__global__ void __launch_bounds__(128, 2)
attn_kernel(const float* __restrict__ q, const float* __restrict__ k,
            const float* __restrict__ v, float* __restrict__ out) {
    __shared__ uint32_t sK2[2][BN * KS2];        // double-buffered K tile (half2 along d)
    __shared__ uint32_t sV2[2][(BN / 2) * VS2];  // double-buffered V tile (half2 along kv)

    const int tid = threadIdx.x;
    const int warp = tid >> 5;
    const int lane = tid & 31;
    const int g = lane >> 2;
    const int t = lane & 3;
    const int base = warp * 32;
    const int rA0 = base + g;
    const int rA1 = base + 16 + g;

    const int bh = blockIdx.y;
    const int b  = bh >> 4;          // H = 16
    const int q0 = blockIdx.x * BM;

    const float* qg = q + ((size_t)bh * Sv + q0) * Dv;
    const float* kg = k + (size_t)bh * Sv * Dv;
    const float* vg = v + (size_t)bh * Sv * Dv;
    float*       og = out + ((size_t)bh * Sv + q0) * Dv;

    // packed-mask pointer: lane <-> row (base+lane), advance one col_group per tile
    const uint32_t* pmp = d_pm + ((size_t)b * (Sv / 32)) * Sv + q0 + base + lane;

    // ---- Q A-fragments for both row-frags: scaled + converted ONCE (32 regs) ----
    uint32_t qh[2][4][4];
#pragma unroll
    for (int f = 0; f < 2; f++) {
        const int rA = base + f * 16 + g, rB = rA + 8;
#pragma unroll
        for (int kc = 0; kc < 4; kc++) {
            const int kk = kc * 16 + 2 * t;
            float2 x0 = *reinterpret_cast<const float2*>(qg + (size_t)rA * Dv + kk);
            float2 x1 = *reinterpret_cast<const float2*>(qg + (size_t)rB * Dv + kk);
            float2 x2 = *reinterpret_cast<const float2*>(qg + (size_t)rA * Dv + kk + 8);
            float2 x3 = *reinterpret_cast<const float2*>(qg + (size_t)rB * Dv + kk + 8);
            qh[f][kc][0] = h2(x0.x * QSCALE, x0.y * QSCALE);
            qh[f][kc][1] = h2(x1.x * QSCALE, x1.y * QSCALE);
            qh[f][kc][2] = h2(x2.x * QSCALE, x2.y * QSCALE);
            qh[f][kc][3] = h2(x3.x * QSCALE, x3.y * QSCALE);
        }
    }

    // Stage mappings + hoisted incrementing pointers
    const int kro = tid >> 2, kds = tid & 3;
    const int vk2 = tid >> 3, vsg = tid & 7;
    const float* kp  = kg + (size_t)kro * Dv + kds * 16;
    const float* vp0 = vg + (size_t)(2 * vk2) * Dv + vsg * 8;
    const float* vp1 = vp0 + Dv;

    // ---- prefetch tile 0 into registers ----
    float4 fkA = *reinterpret_cast<const float4*>(kp);
    float4 fkB = *reinterpret_cast<const float4*>(kp + 4);
    float4 fkC = *reinterpret_cast<const float4*>(kp + 8);
    float4 fkD = *reinterpret_cast<const float4*>(kp + 12);
    float4 fvA0 = *reinterpret_cast<const float4*>(vp0);
    float4 fvA1 = *reinterpret_cast<const float4*>(vp0 + 4);
    float4 fvB0 = *reinterpret_cast<const float4*>(vp1);
    float4 fvB1 = *reinterpret_cast<const float4*>(vp1 + 4);
    kp += BN * Dv; vp0 += BN * Dv; vp1 += BN * Dv;

    float o0[8][4], o1[8][4];
#pragma unroll
    for (int i = 0; i < 8; i++)
#pragma unroll
        for (int j = 0; j < 4; j++) { o0[i][j] = 0.f; o1[i][j] = 0.f; }
    float m0 = -1e30f, m1 = -1e30f, m2 = -1e30f, m3 = -1e30f;
    float l0 = 0.f, l1 = 0.f, l2 = 0.f, l3 = 0.f;

    for (int kt = 0; kt < NT; kt++) {
        const int cur = kt & 1;

        // ---- mask word for this tile: one coalesced LDG.32 per warp ----
        uint32_t pmw = *pmp;
        pmp += Sv;

        // ---- store prefetched regs -> smem[cur] (convert f32 -> half2 here) ----
        {
            uint32_t* dK = &sK2[cur][kro * KS2 + kds * 8];
            *reinterpret_cast<uint4*>(dK) =
                make_uint4(h2(fkA.x, fkA.y), h2(fkA.z, fkA.w), h2(fkB.x, fkB.y), h2(fkB.z, fkB.w));
            *reinterpret_cast<uint4*>(dK + 4) =
                make_uint4(h2(fkC.x, fkC.y), h2(fkC.z, fkC.w), h2(fkD.x, fkD.y), h2(fkD.z, fkD.w));
            uint32_t* dV = &sV2[cur][vk2 * VS2 + vsg * 8];
            *reinterpret_cast<uint4*>(dV) =
                make_uint4(h2(fvA0.x, fvB0.x), h2(fvA0.y, fvB0.y), h2(fvA0.z, fvB0.z), h2(fvA0.w, fvB0.w));
            *reinterpret_cast<uint4*>(dV + 4) =
                make_uint4(h2(fvA1.x, fvB1.x), h2(fvA1.y, fvB1.y), h2(fvA1.z, fvB1.z), h2(fvA1.w, fvB1.w));
        }
        __syncthreads();  // single barrier per iteration (double buffer)

        // ---- prefetch NEXT tile into regs: LDGs hidden under the compute below ----
        if (kt + 1 < NT) {
            fkA = *reinterpret_cast<const float4*>(kp);
            fkB = *reinterpret_cast<const float4*>(kp + 4);
            fkC = *reinterpret_cast<const float4*>(kp + 8);
            fkD = *reinterpret_cast<const float4*>(kp + 12);
            fvA0 = *reinterpret_cast<const float4*>(vp0);
            fvA1 = *reinterpret_cast<const float4*>(vp0 + 4);
            fvB0 = *reinterpret_cast<const float4*>(vp1);
            fvB1 = *reinterpret_cast<const float4*>(vp1 + 4);
            kp += BN * Dv; vp0 += BN * Dv; vp1 += BN * Dv;
        }

        // ---- redistribute mask words to fragment rows (4 SHFL per warp) ----
        const uint32_t wA0 = __shfl_sync(0xffffffffu, pmw, g);
        const uint32_t wB0 = __shfl_sync(0xffffffffu, pmw, g + 8);
        const uint32_t wA1 = __shfl_sync(0xffffffffu, pmw, g + 16);
        const uint32_t wB1 = __shfl_sync(0xffffffffu, pmw, g + 24);
        const int sh = 2 * t;

        // ---- S = Q @ K^T: each b-frag load feeds BOTH row-frags ----
        float s0[4][4], s1[4][4];
#pragma unroll
        for (int nc = 0; nc < 4; nc++)
#pragma unroll
            for (int j = 0; j < 4; j++) { s0[nc][j] = 0.f; s1[nc][j] = 0.f; }

#pragma unroll
        for (int kc = 0; kc < 4; kc++) {
#pragma unroll
            for (int nc = 0; nc < 4; nc++) {
                uint32_t bv[2] = {sK2[cur][(nc * 8 + g) * KS2 + kc * 8 + t],
                                  sK2[cur][(nc * 8 + g) * KS2 + kc * 8 + t + 4]};
                mma16(s0[nc], qh[0][kc], bv);
                mma16(s1[nc], qh[1][kc], bv);
            }
        }

        // ---- softmax frag0 -> register-resident P ----
        uint32_t pa0[4][2];
        {
            float mx0 = -1e30f, mx1 = -1e30f;
#pragma unroll
            for (int nc = 0; nc < 4; nc++) {
                const int c = nc * 8 + sh;
                s0[nc][0] = ((wA0 >> c) & 1u) ? s0[nc][0] : -1e9f;
                s0[nc][1] = ((wA0 >> (c + 1)) & 1u) ? s0[nc][1] : -1e9f;
                s0[nc][2] = ((wB0 >> c) & 1u) ? s0[nc][2] : -1e9f;
                s0[nc][3] = ((wB0 >> (c + 1)) & 1u) ? s0[nc][3] : -1e9f;
                mx0 = fmaxf(mx0, fmaxf(s0[nc][0], s0[nc][1]));
                mx1 = fmaxf(mx1, fmaxf(s0[nc][2], s0[nc][3]));
            }
            mx0 = fmaxf(mx0, __shfl_xor_sync(0xffffffffu, mx0, 1));
            mx0 = fmaxf(mx0, __shfl_xor_sync(0xffffffffu, mx0, 2));
            mx1 = fmaxf(mx1, __shfl_xor_sync(0xffffffffu, mx1, 1));
            mx1 = fmaxf(mx1, __shfl_xor_sync(0xffffffffu, mx1, 2));
            float mn0 = fmaxf(m0, mx0), mn1 = fmaxf(m1, mx1);
            float a0 = exp2f(m0 - mn0), a1 = exp2f(m1 - mn1);
            m0 = mn0; m1 = mn1;
            float rs0 = 0.f, rs1 = 0.f;
#pragma unroll
            for (int nc = 0; nc < 4; nc++) {
                float p00 = exp2f(s0[nc][0] - mn0);
                float p01 = exp2f(s0[nc][1] - mn0);
                float p10 = exp2f(s0[nc][2] - mn1);
                float p11 = exp2f(s0[nc][3] - mn1);
                rs0 += p00 + p01; rs1 += p10 + p11;
                pa0[nc][0] = h2(p00, p01);
                pa0[nc][1] = h2(p10, p11);
            }
            rs0 += __shfl_xor_sync(0xffffffffu, rs0, 1);
            rs0 += __shfl_xor_sync(0xffffffffu, rs0, 2);
            rs1 += __shfl_xor_sync(0xffffffffu, rs1, 1);
            rs1 += __shfl_xor_sync(0xffffffffu, rs1, 2);
            l0 = l0 * a0 + rs0;
            l1 = l1 * a1 + rs1;
            if (__any_sync(0xffffffffu, (a0 < 1.f) | (a1 < 1.f))) {
#pragma unroll
                for (int nc = 0; nc < 8; nc++) {
                    o0[nc][0] *= a0; o0[nc][1] *= a0;
                    o0[nc][2] *= a1; o0[nc][3] *= a1;
                }
            }
        }

        // ---- softmax frag1 ----
        uint32_t pa1[4][2];
        {
            float mx0 = -1e30f, mx1 = -1e30f;
#pragma unroll
            for (int nc = 0; nc < 4; nc++) {
                const int c = nc * 8 + sh;
                s1[nc][0] = ((wA1 >> c) & 1u) ? s1[nc][0] : -1e9f;
                s1[nc][1] = ((wA1 >> (c + 1)) & 1u) ? s1[nc][1] : -1e9f;
                s1[nc][2] = ((wB1 >> c) & 1u) ? s1[nc][2] : -1e9f;
                s1[nc][3] = ((wB1 >> (c + 1)) & 1u) ? s1[nc][3] : -1e9f;
                mx0 = fmaxf(mx0, fmaxf(s1[nc][0], s1[nc][1]));
                mx1 = fmaxf(mx1, fmaxf(s1[nc][2], s1[nc][3]));
            }
            mx0 = fmaxf(mx0, __shfl_xor_sync(0xffffffffu, mx0, 1));
            mx0 = fmaxf(mx0, __shfl_xor_sync(0xffffffffu, mx0, 2));
            mx1 = fmaxf(mx1, __shfl_xor_sync(0xffffffffu, mx1, 1));
            mx1 = fmaxf(mx1, __shfl_xor_sync(0xffffffffu, mx1, 2));
            float mn0 = fmaxf(m2, mx0), mn1 = fmaxf(m3, mx1);
            float a0 = exp2f(m2 - mn0), a1 = exp2f(m3 - mn1);
            m2 = mn0; m3 = mn1;
            float rs0 = 0.f, rs1 = 0.f;
#pragma unroll
            for (int nc = 0; nc < 4; nc++) {
                float p00 = exp2f(s1[nc][0] - mn0);
                float p01 = exp2f(s1[nc][1] - mn0);
                float p10 = exp2f(s1[nc][2] - mn1);
                float p11 = exp2f(s1[nc][3] - mn1);
                rs0 += p00 + p01; rs1 += p10 + p11;
                pa1[nc][0] = h2(p00, p01);
                pa1[nc][1] = h2(p10, p11);
            }
            rs0 += __shfl_xor_sync(0xffffffffu, rs0, 1);
            rs0 += __shfl_xor_sync(0xffffffffu, rs0, 2);
            rs1 += __shfl_xor_sync(0xffffffffu, rs1, 1);
            rs1 += __shfl_xor_sync(0xffffffffu, rs1, 2);
            l2 = l2 * a0 + rs0;
            l3 = l3 * a1 + rs1;
            if (__any_sync(0xffffffffu, (a0 < 1.f) | (a1 < 1.f))) {
#pragma unroll
                for (int nc = 0; nc < 8; nc++) {
                    o1[nc][0] *= a0; o1[nc][1] *= a0;
                    o1[nc][2] *= a1; o1[nc][3] *= a1;
                }
            }
        }

        // ---- O += P @ V: each pb load feeds BOTH row-frags ----
#pragma unroll
        for (int kc2 = 0; kc2 < 2; kc2++) {
            uint32_t a0v[4] = {pa0[2 * kc2][0], pa0[2 * kc2][1],
                               pa0[2 * kc2 + 1][0], pa0[2 * kc2 + 1][1]};
            uint32_t a1v[4] = {pa1[2 * kc2][0], pa1[2 * kc2][1],
                               pa1[2 * kc2 + 1][0], pa1[2 * kc2 + 1][1]};
#pragma unroll
            for (int nc = 0; nc < 8; nc++) {
                uint32_t pb[2] = {sV2[cur][(kc2 * 8 + t) * VS2 + nc * 8 + g],
                                  sV2[cur][(kc2 * 8 + t + 4) * VS2 + nc * 8 + g]};
                mma16(o0[nc], a0v, pb);
                mma16(o1[nc], a1v, pb);
            }
        }
    }

    // ---- epilogue ----
    {
        float i0 = 1.f / l0, i1 = 1.f / l1, i2 = 1.f / l2, i3 = 1.f / l3;
#pragma unroll
        for (int nc = 0; nc < 8; nc++) {
            int c0 = nc * 8 + 2 * t;
            *reinterpret_cast<float2*>(og + (size_t)rA0 * Dv + c0) =
                make_float2(o0[nc][0] * i0, o0[nc][1] * i0);
            *reinterpret_cast<float2*>(og + (size_t)(rA0 + 8) * Dv + c0) =
                make_float2(o0[nc][2] * i1, o0[nc][3] * i1);
            *reinterpret_cast<float2*>(og + (size_t)rA1 * Dv + c0) =
                make_float2(o1[nc][0] * i2, o1[nc][1] * i2);
            *reinterpret_cast<float2*>(og + (size_t)(rA1 + 8) * Dv + c0) =
                make_float2(o1[nc][2] * i3, o1[nc][3] * i3);
        }
    }
}

}  // namespace

extern "C" void kernel_launch(void* const* d_in, const int* in_sizes, int n_in,
                              void* d_out, int out_size) {
    const float* q = (const float*)d_in[0];
    const float* k = (const float*)d_in[1];
    const float* v = (const float*)d_in[2];
    const int* mask = (const int*)d_in[3];
    float* out = (float*)d_out;

    // Pre-pass: pack mask int32 -> bits (tile-major layout), ~8 us
    int total_threads = Bv * (Sv / 32) * Sv * 32;  // one warp per packed word
    pack_mask_kernel<<<total_threads / 256, 256>>>(mask);

    dim3 grid(Sv / BM, Bv * Hv);  // (16, 32)
    dim3 block(128);
    attn_kernel<<<grid, block>>>(q, k, v, out);
}

// round 15
// speedup vs baseline: 6.0040x; 1.1301x over previous
#include <cuda_runtime.h>
#include <cuda_fp16.h>
#include <cstdint>

namespace {

constexpr int Bv = 2, Hv = 16, Sv = 2048, Dv = 64;
constexpr int BM = 128;   // query rows per CTA (32 per warp)
constexpr int BN = 32;    // kv rows per tile
constexpr int NT = Sv / BN;
constexpr int KS2 = 36;   // sK2 half2 stride: frag banks (4g+t), conflict-free
constexpr int VS2 = 72;   // sV2 half2 stride: frag banks (8t+g), conflict-free
constexpr float QSCALE = 0.125f * 1.44269504089f;  // 1/sqrt(64) * log2(e)

// Packed mask bits: pm[b][col_group][row], col_group = 32 cols. 1 MB scratch.
__device__ uint32_t d_pm[(size_t)Bv * (Sv / 32) * Sv];

// 8 lanes per packed word; each lane loads int4 (4 cols) and contributes a nibble.
__global__ void __launch_bounds__(256)
pack_mask_kernel(const int* __restrict__ mask) {
    int gtid = blockIdx.x * 256 + threadIdx.x;
    int w   = gtid >> 3;                 // word index = (b*64 + cg)*2048 + row
    int sub = gtid & 7;
    int row = w & (Sv - 1);
    int cg  = (w >> 11) & (Sv / 32 - 1);
    int b   = w >> 17;
    int4 v = *reinterpret_cast<const int4*>(
        mask + ((size_t)b * Sv + row) * Sv + cg * 32 + sub * 4);
    uint32_t nib = (v.x != 0 ? 1u : 0u) | (v.y != 0 ? 2u : 0u) |
                   (v.z != 0 ? 4u : 0u) | (v.w != 0 ? 8u : 0u);
    uint32_t val = nib << (4 * sub);
    val |= __shfl_xor_sync(0xffffffffu, val, 1);
    val |= __shfl_xor_sync(0xffffffffu, val, 2);
    val |= __shfl_xor_sync(0xffffffffu, val, 4);
    if (sub == 0) d_pm[w] = val;
}

__device__ __forceinline__ uint32_t h2(float lo, float hi) {
    __half2 h = __floats2half2_rn(lo, hi);
    return *reinterpret_cast<uint32_t*>(&h);
}

__device__ __forceinline__ void mma16(float* c, const uint32_t* a, const uint32_t* b) {
    asm volatile(
        "mma.sync.aligned.m16n8k16.row.col.f32.f16.f16.f32 "
        "{%0,%1,%2,%3}, {%4,%5,%6,%7}, {%8,%9}, {%0,%1,%2,%3};"
        : "+f"(c[0]), "+f"(c[1]), "+f"(c[2]), "+f"(c[3])
        : "r"(a[0]), "r"(a[1]), "r"(a[2]), "r"(a[3]), "r"(b[0]), "r"(b[1]));
}

__global__ void __launch_bounds__(128, 2)
attn_kernel(const float* __restrict__ q, const float* __restrict__ k,
            const float* __restrict__ v, float* __restrict__ out) {
    __shared__ uint32_t sK2[2][BN * KS2];        // double-buffered K tile (half2 along d)
    __shared__ uint32_t sV2[2][(BN / 2) * VS2];  // double-buffered V tile (half2 along kv)

    const int tid = threadIdx.x;
    const int warp = tid >> 5;
    const int lane = tid & 31;
    const int g = lane >> 2;
    const int t = lane & 3;
    const int base = warp * 32;
    const int rA0 = base + g;
    const int rA1 = base + 16 + g;

    const int bh = blockIdx.y;
    const int b  = bh >> 4;          // H = 16
    const int q0 = blockIdx.x * BM;

    const float* qg = q + ((size_t)bh * Sv + q0) * Dv;
    const float* kg = k + (size_t)bh * Sv * Dv;
    const float* vg = v + (size_t)bh * Sv * Dv;
    float*       og = out + ((size_t)bh * Sv + q0) * Dv;

    // packed-mask pointer: lane <-> row (base+lane), advance one col_group per tile
    const uint32_t* pmp = d_pm + ((size_t)b * (Sv / 32)) * Sv + q0 + base + lane;

    // ---- Q A-fragments for both row-frags: scaled + converted ONCE (32 regs) ----
    uint32_t qh[2][4][4];
#pragma unroll
    for (int f = 0; f < 2; f++) {
        const int rA = base + f * 16 + g, rB = rA + 8;
#pragma unroll
        for (int kc = 0; kc < 4; kc++) {
            const int kk = kc * 16 + 2 * t;
            float2 x0 = *reinterpret_cast<const float2*>(qg + (size_t)rA * Dv + kk);
            float2 x1 = *reinterpret_cast<const float2*>(qg + (size_t)rB * Dv + kk);
            float2 x2 = *reinterpret_cast<const float2*>(qg + (size_t)rA * Dv + kk + 8);
            float2 x3 = *reinterpret_cast<const float2*>(qg + (size_t)rB * Dv + kk + 8);
            qh[f][kc][0] = h2(x0.x * QSCALE, x0.y * QSCALE);
            qh[f][kc][1] = h2(x1.x * QSCALE, x1.y * QSCALE);
            qh[f][kc][2] = h2(x2.x * QSCALE, x2.y * QSCALE);
            qh[f][kc][3] = h2(x3.x * QSCALE, x3.y * QSCALE);
        }
    }

    // Stage mappings + hoisted incrementing pointers
    const int kro = tid >> 2, kds = tid & 3;
    const int vk2 = tid >> 3, vsg = tid & 7;
    const float* kp  = kg + (size_t)kro * Dv + kds * 16;
    const float* vp0 = vg + (size_t)(2 * vk2) * Dv + vsg * 8;
    const float* vp1 = vp0 + Dv;

    // ---- prefetch tile 0 (K/V + mask word) into registers ----
    float4 fkA = *reinterpret_cast<const float4*>(kp);
    float4 fkB = *reinterpret_cast<const float4*>(kp + 4);
    float4 fkC = *reinterpret_cast<const float4*>(kp + 8);
    float4 fkD = *reinterpret_cast<const float4*>(kp + 12);
    float4 fvA0 = *reinterpret_cast<const float4*>(vp0);
    float4 fvA1 = *reinterpret_cast<const float4*>(vp0 + 4);
    float4 fvB0 = *reinterpret_cast<const float4*>(vp1);
    float4 fvB1 = *reinterpret_cast<const float4*>(vp1 + 4);
    kp += BN * Dv; vp0 += BN * Dv; vp1 += BN * Dv;
    uint32_t pmw = *pmp;
    pmp += Sv;

    float o0[8][4], o1[8][4];
#pragma unroll
    for (int i = 0; i < 8; i++)
#pragma unroll
        for (int j = 0; j < 4; j++) { o0[i][j] = 0.f; o1[i][j] = 0.f; }
    float m0 = -1e30f, m1 = -1e30f, m2 = -1e30f, m3 = -1e30f;
    // l* are PER-THREAD PARTIAL sums (this thread's columns); reduced in epilogue.
    float l0 = 0.f, l1 = 0.f, l2 = 0.f, l3 = 0.f;

    for (int kt = 0; kt < NT; kt++) {
        const int cur = kt & 1;

        // ---- store prefetched regs -> smem[cur] (convert f32 -> half2 here) ----
        {
            uint32_t* dK = &sK2[cur][kro * KS2 + kds * 8];
            *reinterpret_cast<uint4*>(dK) =
                make_uint4(h2(fkA.x, fkA.y), h2(fkA.z, fkA.w), h2(fkB.x, fkB.y), h2(fkB.z, fkB.w));
            *reinterpret_cast<uint4*>(dK + 4) =
                make_uint4(h2(fkC.x, fkC.y), h2(fkC.z, fkC.w), h2(fkD.x, fkD.y), h2(fkD.z, fkD.w));
            uint32_t* dV = &sV2[cur][vk2 * VS2 + vsg * 8];
            *reinterpret_cast<uint4*>(dV) =
                make_uint4(h2(fvA0.x, fvB0.x), h2(fvA0.y, fvB0.y), h2(fvA0.z, fvB0.z), h2(fvA0.w, fvB0.w));
            *reinterpret_cast<uint4*>(dV + 4) =
                make_uint4(h2(fvA1.x, fvB1.x), h2(fvA1.y, fvB1.y), h2(fvA1.z, fvB1.z), h2(fvA1.w, fvB1.w));
        }
        __syncthreads();  // single barrier per iteration (double buffer)

        const uint32_t pmwc = pmw;

        // ---- prefetch NEXT tile into regs: LDGs hidden under the compute below ----
        if (kt + 1 < NT) {
            fkA = *reinterpret_cast<const float4*>(kp);
            fkB = *reinterpret_cast<const float4*>(kp + 4);
            fkC = *reinterpret_cast<const float4*>(kp + 8);
            fkD = *reinterpret_cast<const float4*>(kp + 12);
            fvA0 = *reinterpret_cast<const float4*>(vp0);
            fvA1 = *reinterpret_cast<const float4*>(vp0 + 4);
            fvB0 = *reinterpret_cast<const float4*>(vp1);
            fvB1 = *reinterpret_cast<const float4*>(vp1 + 4);
            kp += BN * Dv; vp0 += BN * Dv; vp1 += BN * Dv;
            pmw = *pmp;
            pmp += Sv;
        }

        // ---- redistribute mask words to fragment rows (4 SHFL per warp) ----
        const uint32_t wA0 = __shfl_sync(0xffffffffu, pmwc, g);
        const uint32_t wB0 = __shfl_sync(0xffffffffu, pmwc, g + 8);
        const uint32_t wA1 = __shfl_sync(0xffffffffu, pmwc, g + 16);
        const uint32_t wB1 = __shfl_sync(0xffffffffu, pmwc, g + 24);
        const int sh = 2 * t;

        // ---- S = Q @ K^T: each b-frag load feeds BOTH row-frags ----
        float s0[4][4], s1[4][4];
#pragma unroll
        for (int nc = 0; nc < 4; nc++)
#pragma unroll
            for (int j = 0; j < 4; j++) { s0[nc][j] = 0.f; s1[nc][j] = 0.f; }

#pragma unroll
        for (int kc = 0; kc < 4; kc++) {
#pragma unroll
            for (int nc = 0; nc < 4; nc++) {
                uint32_t bv[2] = {sK2[cur][(nc * 8 + g) * KS2 + kc * 8 + t],
                                  sK2[cur][(nc * 8 + g) * KS2 + kc * 8 + t + 4]};
                mma16(s0[nc], qh[0][kc], bv);
                mma16(s1[nc], qh[1][kc], bv);
            }
        }

        // ---- softmax frag0 -> register-resident P (l kept as thread-partials) ----
        uint32_t pa0[4][2];
        {
            float mx0 = -1e30f, mx1 = -1e30f;
#pragma unroll
            for (int nc = 0; nc < 4; nc++) {
                const int c = nc * 8 + sh;
                s0[nc][0] = ((wA0 >> c) & 1u) ? s0[nc][0] : -1e9f;
                s0[nc][1] = ((wA0 >> (c + 1)) & 1u) ? s0[nc][1] : -1e9f;
                s0[nc][2] = ((wB0 >> c) & 1u) ? s0[nc][2] : -1e9f;
                s0[nc][3] = ((wB0 >> (c + 1)) & 1u) ? s0[nc][3] : -1e9f;
                mx0 = fmaxf(mx0, fmaxf(s0[nc][0], s0[nc][1]));
                mx1 = fmaxf(mx1, fmaxf(s0[nc][2], s0[nc][3]));
            }
            mx0 = fmaxf(mx0, __shfl_xor_sync(0xffffffffu, mx0, 1));
            mx0 = fmaxf(mx0, __shfl_xor_sync(0xffffffffu, mx0, 2));
            mx1 = fmaxf(mx1, __shfl_xor_sync(0xffffffffu, mx1, 1));
            mx1 = fmaxf(mx1, __shfl_xor_sync(0xffffffffu, mx1, 2));
            float mn0 = fmaxf(m0, mx0), mn1 = fmaxf(m1, mx1);
            float a0 = exp2f(m0 - mn0), a1 = exp2f(m1 - mn1);
            m0 = mn0; m1 = mn1;
            float rs0 = 0.f, rs1 = 0.f;
#pragma unroll
            for (int nc = 0; nc < 4; nc++) {
                float p00 = exp2f(s0[nc][0] - mn0);
                float p01 = exp2f(s0[nc][1] - mn0);
                float p10 = exp2f(s0[nc][2] - mn1);
                float p11 = exp2f(s0[nc][3] - mn1);
                rs0 += p00 + p01; rs1 += p10 + p11;
                pa0[nc][0] = h2(p00, p01);
                pa0[nc][1] = h2(p10, p11);
            }
            l0 = l0 * a0 + rs0;     // partial (no lane reduction here)
            l1 = l1 * a1 + rs1;
            if (__any_sync(0xffffffffu, (a0 < 1.f) | (a1 < 1.f))) {
#pragma unroll
                for (int nc = 0; nc < 8; nc++) {
                    o0[nc][0] *= a0; o0[nc][1] *= a0;
                    o0[nc][2] *= a1; o0[nc][3] *= a1;
                }
            }
        }

        // ---- softmax frag1 ----
        uint32_t pa1[4][2];
        {
            float mx0 = -1e30f, mx1 = -1e30f;
#pragma unroll
            for (int nc = 0; nc < 4; nc++) {
                const int c = nc * 8 + sh;
                s1[nc][0] = ((wA1 >> c) & 1u) ? s1[nc][0] : -1e9f;
                s1[nc][1] = ((wA1 >> (c + 1)) & 1u) ? s1[nc][1] : -1e9f;
                s1[nc][2] = ((wB1 >> c) & 1u) ? s1[nc][2] : -1e9f;
                s1[nc][3] = ((wB1 >> (c + 1)) & 1u) ? s1[nc][3] : -1e9f;
                mx0 = fmaxf(mx0, fmaxf(s1[nc][0], s1[nc][1]));
                mx1 = fmaxf(mx1, fmaxf(s1[nc][2], s1[nc][3]));
            }
            mx0 = fmaxf(mx0, __shfl_xor_sync(0xffffffffu, mx0, 1));
            mx0 = fmaxf(mx0, __shfl_xor_sync(0xffffffffu, mx0, 2));
            mx1 = fmaxf(mx1, __shfl_xor_sync(0xffffffffu, mx1, 1));
            mx1 = fmaxf(mx1, __shfl_xor_sync(0xffffffffu, mx1, 2));
            float mn0 = fmaxf(m2, mx0), mn1 = fmaxf(m3, mx1);
            float a0 = exp2f(m2 - mn0), a1 = exp2f(m3 - mn1);
            m2 = mn0; m3 = mn1;
            float rs0 = 0.f, rs1 = 0.f;
#pragma unroll
            for (int nc = 0; nc < 4; nc++) {
                float p00 = exp2f(s1[nc][0] - mn0);
                float p01 = exp2f(s1[nc][1] - mn0);
                float p10 = exp2f(s1[nc][2] - mn1);
                float p11 = exp2f(s1[nc][3] - mn1);
                rs0 += p00 + p01; rs1 += p10 + p11;
                pa1[nc][0] = h2(p00, p01);
                pa1[nc][1] = h2(p10, p11);
            }
            l2 = l2 * a0 + rs0;
            l3 = l3 * a1 + rs1;
            if (__any_sync(0xffffffffu, (a0 < 1.f) | (a1 < 1.f))) {
#pragma unroll
                for (int nc = 0; nc < 8; nc++) {
                    o1[nc][0] *= a0; o1[nc][1] *= a0;
                    o1[nc][2] *= a1; o1[nc][3] *= a1;
                }
            }
        }

        // ---- O += P @ V: each pb load feeds BOTH row-frags ----
#pragma unroll
        for (int kc2 = 0; kc2 < 2; kc2++) {
            uint32_t a0v[4] = {pa0[2 * kc2][0], pa0[2 * kc2][1],
                               pa0[2 * kc2 + 1][0], pa0[2 * kc2 + 1][1]};
            uint32_t a1v[4] = {pa1[2 * kc2][0], pa1[2 * kc2][1],
                               pa1[2 * kc2 + 1][0], pa1[2 * kc2 + 1][1]};
#pragma unroll
            for (int nc = 0; nc < 8; nc++) {
                uint32_t pb[2] = {sV2[cur][(kc2 * 8 + t) * VS2 + nc * 8 + g],
                                  sV2[cur][(kc2 * 8 + t + 4) * VS2 + nc * 8 + g]};
                mma16(o0[nc], a0v, pb);
                mma16(o1[nc], a1v, pb);
            }
        }
    }

    // ---- epilogue: reduce l partials across the quad, then scale + store ----
    {
        l0 += __shfl_xor_sync(0xffffffffu, l0, 1);
        l0 += __shfl_xor_sync(0xffffffffu, l0, 2);
        l1 += __shfl_xor_sync(0xffffffffu, l1, 1);
        l1 += __shfl_xor_sync(0xffffffffu, l1, 2);
        l2 += __shfl_xor_sync(0xffffffffu, l2, 1);
        l2 += __shfl_xor_sync(0xffffffffu, l2, 2);
        l3 += __shfl_xor_sync(0xffffffffu, l3, 1);
        l3 += __shfl_xor_sync(0xffffffffu, l3, 2);
        float i0 = 1.f / l0, i1 = 1.f / l1, i2 = 1.f / l2, i3 = 1.f / l3;
#pragma unroll
        for (int nc = 0; nc < 8; nc++) {
            int c0 = nc * 8 + 2 * t;
            *reinterpret_cast<float2*>(og + (size_t)rA0 * Dv + c0) =
                make_float2(o0[nc][0] * i0, o0[nc][1] * i0);
            *reinterpret_cast<float2*>(og + (size_t)(rA0 + 8) * Dv + c0) =
                make_float2(o0[nc][2] * i1, o0[nc][3] * i1);
            *reinterpret_cast<float2*>(og + (size_t)rA1 * Dv + c0) =
                make_float2(o1[nc][0] * i2, o1[nc][1] * i2);
            *reinterpret_cast<float2*>(og + (size_t)(rA1 + 8) * Dv + c0) =
                make_float2(o1[nc][2] * i3, o1[nc][3] * i3);
        }
    }
}

}  // namespace

extern "C" void kernel_launch(void* const* d_in, const int* in_sizes, int n_in,
                              void* d_out, int out_size) {
    const float* q = (const float*)d_in[0];
    const float* k = (const float*)d_in[1];
    const float* v = (const float*)d_in[2];
    const int* mask = (const int*)d_in[3];
    float* out = (float*)d_out;

    // Pre-pass: pack mask int32 -> bits (tile-major layout), int4 + nibble OR
    int total_threads = Bv * (Sv / 32) * Sv * 8;  // 8 lanes per packed word
    pack_mask_kernel<<<total_threads / 256, 256>>>(mask);

    dim3 grid(Sv / BM, Bv * Hv);  // (16, 32)
    dim3 block(128);
    attn_kernel<<<grid, block>>>(q, k, v, out);
}